// round 8
// baseline (speedup 1.0000x reference)
#include <cuda_runtime.h>
#include <cuda_fp16.h>
#include <math.h>

#define TT 12
#define NN 20000
#define EE 400000
#define FF 32
#define HH 64
#define OO 8

// Output layout (flattened tuple): out[4,N,8] | c2[N,64] | emb[T,N,64]
#define OUT_OFF 0
#define C2_OFF  (4*NN*OO)                 // 640000
#define EMB_OFF (C2_OFF + NN*HH)          // 1920000

#define N_TILES (NN / 32)                 // 625 (exact)
#define PRE_TILES (TT * NN / 128)         // 1875 (exact)

// ---------------- scratch (static device globals; allocation-free at runtime) ----
__device__ int      g_rowptr[NN + 1];
__device__ int      g_cursor[NN];
__device__ int      g_csr_src[EE];
__device__ float    g_csr_w[EE];
__device__ unsigned g_xrh[TT * NN * 32];         // relu(emb) as half2 pairs
__device__ unsigned g_preh[2][TT * NN * 128];    // gate pre-contrib, half2 pairs
__device__ unsigned g_hh[2][NN * 32];            // fp16 hidden state (half2 words)
__device__ float    g_c[NN * HH];
__device__ float    g_h2last[4 * NN * HH];       // h2 for last 4 steps (fp32)

// grid barrier state
__device__ unsigned g_bar_count = 0;
__device__ volatile unsigned g_bar_gen = 0;

// ---------------- helpers ----------------------------------------------------------
__device__ __forceinline__ void mma16(float* c, const uint4 a, const uint2 b) {
    asm volatile(
        "mma.sync.aligned.m16n8k16.row.col.f32.f16.f16.f32 "
        "{%0,%1,%2,%3},{%4,%5,%6,%7},{%8,%9},{%0,%1,%2,%3};"
        : "+f"(c[0]), "+f"(c[1]), "+f"(c[2]), "+f"(c[3])
        : "r"(a.x), "r"(a.y), "r"(a.z), "r"(a.w), "r"(b.x), "r"(b.y));
}
__device__ __forceinline__ unsigned h2u(float lo, float hi) {
    __half2 h = __floats2half2_rn(lo, hi);
    return *(unsigned*)&h;
}
__device__ __forceinline__ float2 u2f2(unsigned u) {
    return __half22float2(*(const __half2*)&u);
}
__device__ __forceinline__ unsigned long long pk2(float lo, float hi) {
    unsigned long long r;
    asm("mov.b64 %0, {%1,%2};" : "=l"(r) : "f"(lo), "f"(hi));
    return r;
}
__device__ __forceinline__ void upk2(unsigned long long v, float& lo, float& hi) {
    asm("mov.b64 {%0,%1}, %2;" : "=f"(lo), "=f"(hi) : "l"(v));
}
__device__ __forceinline__ unsigned long long ffma2(unsigned long long a,
                                                    unsigned long long b,
                                                    unsigned long long c) {
    unsigned long long d;
    asm("fma.rn.f32x2 %0, %1, %2, %3;" : "=l"(d) : "l"(a), "l"(b), "l"(c));
    return d;
}
__device__ __forceinline__ unsigned ld_acq(volatile unsigned* p) {
    unsigned v;
    asm volatile("ld.acquire.gpu.u32 %0, [%1];"
                 : "=r"(v) : "l"((const unsigned*)p) : "memory");
    return v;
}
__device__ __forceinline__ void gridbar(unsigned& gen) {
    __syncthreads();
    if (threadIdx.x == 0) {
        __threadfence();
        unsigned t = atomicAdd(&g_bar_count, 1);
        if (t == gridDim.x - 1) {
            g_bar_count = 0;
            __threadfence();
            asm volatile("st.release.gpu.u32 [%0], %1;"
                         :: "l"((unsigned*)&g_bar_gen), "r"(gen + 1) : "memory");
        } else {
            while (ld_acq(&g_bar_gen) != gen + 1) __nanosleep(16);
        }
    }
    gen++;
    __syncthreads();
}

// ---------------- fused CSR builder (persistent, 1 launch) ------------------------
__global__ __launch_bounds__(256, 1) void k_csr(const int* __restrict__ src,
                                                const int* __restrict__ dst,
                                                const float* __restrict__ ew) {
    int tid = threadIdx.x;
    unsigned gen = g_bar_gen;
    // zero cursor
    for (int i = blockIdx.x * 256 + tid; i < NN; i += gridDim.x * 256)
        g_cursor[i] = 0;
    gridbar(gen);
    // degree histogram
    for (int e = blockIdx.x * 256 + tid; e < EE; e += gridDim.x * 256)
        atomicAdd(&g_cursor[dst[e]], 1);
    gridbar(gen);
    // exclusive scan (block 0 only)
    if (blockIdx.x == 0) {
        __shared__ int wsum[8];
        const int CH = 80;  // 256*80 = 20480 >= 20000
        int base = tid * CH;
        int s = 0;
        for (int i = 0; i < CH; i++) {
            int idx = base + i;
            s += (idx < NN) ? g_cursor[idx] : 0;
        }
        int lane = tid & 31, w = tid >> 5;
        int inc = s;
#pragma unroll
        for (int o = 1; o < 32; o <<= 1) {
            int t = __shfl_up_sync(0xffffffffu, inc, o);
            if (lane >= o) inc += t;
        }
        if (lane == 31) wsum[w] = inc;
        __syncthreads();
        if (tid == 0) {
            int acc = 0;
            for (int j = 0; j < 8; j++) {
                int t = wsum[j];
                wsum[j] = acc;
                acc += t;
            }
        }
        __syncthreads();
        int run = (inc - s) + wsum[w];
        for (int i = 0; i < CH; i++) {
            int idx = base + i;
            if (idx < NN) {
                int v = g_cursor[idx];
                g_rowptr[idx] = run;
                g_cursor[idx] = run;
                run += v;
            }
        }
        if (tid == 0) g_rowptr[NN] = EE;
    }
    gridbar(gen);
    // fill
    for (int e = blockIdx.x * 256 + tid; e < EE; e += gridDim.x * 256) {
        int d = dst[e];
        int pos = atomicAdd(&g_cursor[d], 1);
        g_csr_src[pos] = src[e];
        g_csr_w[pos] = ew[e];
    }
}

// ---------------- fused SAGE: gather wmean(x) in-tile + f32x2 GEMM (exact fp32) ---
__global__ __launch_bounds__(256, 2) void k_sage(const float* __restrict__ x,
                                                 const float* __restrict__ Wr,
                                                 const float* __restrict__ Wroot,
                                                 const float* __restrict__ b,
                                                 float* __restrict__ emb) {
    __shared__ float sAgg[64][33];
    __shared__ float sA[64][33];
    __shared__ float sW[32][66];
    int m0 = blockIdx.x * 64;
    int tid = threadIdx.x;
    int warp = tid >> 5, lane = tid & 31;
    int tr = tid / 16, tc = tid % 16;

    // gather phase: 8 warps x 8 rows; lane = feature
#pragma unroll 1
    for (int rq = 0; rq < 8; rq++) {
        int r = warp * 8 + rq;
        int m = m0 + r;
        int t = m / NN;
        int n = m - t * NN;
        const float* __restrict__ in = x + (size_t)t * NN * 32;
        int e0 = g_rowptr[n], e1 = g_rowptr[n + 1];
        float acc = 0.f;
        for (int e = e0; e < e1; e += 8) {
            int idx[8];
            float wv[8], vv[8];
#pragma unroll
            for (int j = 0; j < 8; j++) {
                int p = e + j;
                int pc = (p < e1) ? p : (e1 - 1);
                idx[j] = __ldg(&g_csr_src[pc]);
                wv[j] = (p < e1) ? __ldg(&g_csr_w[pc]) : 0.f;
            }
#pragma unroll
            for (int j = 0; j < 8; j++)
                vv[j] = __ldg(&in[(size_t)idx[j] * 32 + lane]);
#pragma unroll
            for (int j = 0; j < 8; j++) acc += wv[j] * vv[j];
        }
        sAgg[r][lane] = acc / (float)max(e1 - e0, 1);
    }
    // stage root rows (x flattened [T*N, 32])
    for (int i = tid; i < 64 * 32; i += 256) {
        int r = i >> 5, k = i & 31;
        sA[r][k] = x[(size_t)(m0 + r) * 32 + k];
    }

    unsigned long long acc[4][2];
#pragma unroll
    for (int i = 0; i < 4; i++)
#pragma unroll
        for (int j2 = 0; j2 < 2; j2++) acc[i][j2] = 0ull;

    for (int kb = 0; kb < 2; kb++) {
        const float* Wsrc = kb ? Wroot : Wr;
        __syncthreads();
        for (int i = tid; i < 32 * 64; i += 256) {
            int r = i >> 6, cc = i & 63;
            sW[r][cc] = Wsrc[(size_t)r * 64 + cc];
        }
        __syncthreads();
        float(*Acur)[33] = kb ? sA : sAgg;
#pragma unroll
        for (int k = 0; k < 32; k++) {
            unsigned long long a2[4];
#pragma unroll
            for (int i = 0; i < 4; i++) {
                float av = Acur[tr * 4 + i][k];
                a2[i] = pk2(av, av);
            }
#pragma unroll
            for (int j2 = 0; j2 < 2; j2++) {
                unsigned long long w2 = *(const unsigned long long*)&sW[k][tc * 4 + j2 * 2];
#pragma unroll
                for (int i = 0; i < 4; i++) acc[i][j2] = ffma2(a2[i], w2, acc[i][j2]);
            }
        }
    }
#pragma unroll
    for (int i = 0; i < 4; i++) {
        int m = m0 + tr * 4 + i;
        size_t mrow = (size_t)m * 64;
#pragma unroll
        for (int j2 = 0; j2 < 2; j2++) {
            float v0, v1;
            upk2(acc[i][j2], v0, v1);
            int c0 = tc * 4 + j2 * 2;
            v0 += b[c0];
            v1 += b[c0 + 1];
            emb[mrow + c0] = v0;
            emb[mrow + c0 + 1] = v1;
            g_xrh[(size_t)m * 32 + (c0 >> 1)] = h2u(fmaxf(v0, 0.f), fmaxf(v1, 0.f));
        }
    }
}

// ---------------- persistent PRE: fused wmean(xr) gather + fp16 mma ---------------
// preh[L] = [wmean(xr)|xr](128 rows/tile) @ [Wr[0:64];Wroot[0:64]](fp16) + b -> fp16
#define PRE_SMEM ((8 * 32 * 32 * 2 + 8 * 8 * 32 * 4) * 4)
__global__ __launch_bounds__(512, 1) void k_pre(const float* __restrict__ Wr1,
                                                const float* __restrict__ Wroot1,
                                                const float* __restrict__ b1,
                                                const float* __restrict__ Wr2,
                                                const float* __restrict__ Wroot2,
                                                const float* __restrict__ b2) {
    extern __shared__ unsigned smem[];
    unsigned* sW = smem;                      // 16384 u32
    unsigned* sA = smem + 8 * 32 * 32 * 2;    // 8192 u32
    int tid = threadIdx.x;
    int warp = tid >> 5, lane = tid & 31;
    int wm = warp >> 2, wn = warp & 3;
    int gid = lane >> 2, tig = lane & 3;

    for (int L = 0; L < 2; L++) {
        const float* __restrict__ Wr = L ? Wr2 : Wr1;
        const float* __restrict__ Wroot = L ? Wroot2 : Wroot1;
        const float* __restrict__ bias = L ? b2 : b1;
        unsigned* __restrict__ preh = g_preh[L];
        __syncthreads();
        for (int i = tid; i < 64 * 256; i += 512) {
            int k2 = i >> 8, n = i & 255;
            int k = k2 * 2;
            float v0, v1;
            if (k < 64) {
                v0 = Wr[(size_t)k * 256 + n];
                v1 = Wr[(size_t)(k + 1) * 256 + n];
            } else {
                v0 = Wroot[(size_t)(k - 64) * 256 + n];
                v1 = Wroot[(size_t)(k - 63) * 256 + n];
            }
            int kc = k2 >> 3, breg = (k2 >> 2) & 1;
            int bl = (n & 7) * 4 + (k2 & 3);
            sW[((kc * 32 + (n >> 3)) * 32 + bl) * 2 + breg] = h2u(v0, v1);
        }
        __syncthreads();

        for (int tile = blockIdx.x; tile < PRE_TILES; tile += gridDim.x) {
            int m0 = tile * 128;
            __syncthreads();
            // fused gather + A staging: 16 warps x 8 rows; lane = feature pair
#pragma unroll 1
            for (int rq = 0; rq < 8; rq++) {
                int r = warp * 8 + rq;
                int m = m0 + r;
                int t = m / NN;
                int n = m - t * NN;
                const unsigned* __restrict__ in = g_xrh + (size_t)t * NN * 32;
                int e0 = g_rowptr[n], e1 = g_rowptr[n + 1];
                float ax = 0.f, ay = 0.f;
                for (int e = e0; e < e1; e += 8) {
                    int idx[8];
                    float wv[8];
                    unsigned uv[8];
#pragma unroll
                    for (int j = 0; j < 8; j++) {
                        int p = e + j;
                        int pc = (p < e1) ? p : (e1 - 1);
                        idx[j] = __ldg(&g_csr_src[pc]);
                        wv[j] = (p < e1) ? __ldg(&g_csr_w[pc]) : 0.f;
                    }
#pragma unroll
                    for (int j = 0; j < 8; j++)
                        uv[j] = __ldg(&in[(size_t)idx[j] * 32 + lane]);
#pragma unroll
                    for (int j = 0; j < 8; j++) {
                        float2 v = u2f2(uv[j]);
                        ax += wv[j] * v.x;
                        ay += wv[j] * v.y;
                    }
                }
                float inv = 1.f / (float)max(e1 - e0, 1);
                unsigned aggu = h2u(ax * inv, ay * inv);
                unsigned hu = in[(size_t)n * 32 + lane];
                int mf = r >> 4;
                int al = (r & 7) * 4 + (lane & 3);
                int regc = ((lane >> 2) & 1) * 2 + ((r >> 3) & 1);
                int kcA = lane >> 3;
                sA[((mf * 8 + kcA) * 32 + al) * 4 + regc] = aggu;
                sA[((mf * 8 + 4 + kcA) * 32 + al) * 4 + regc] = hu;
            }
            __syncthreads();
            float acc[2][4][2][4];
#pragma unroll
            for (int mf = 0; mf < 2; mf++)
#pragma unroll
                for (int g = 0; g < 4; g++)
#pragma unroll
                    for (int hh = 0; hh < 2; hh++)
#pragma unroll
                        for (int q = 0; q < 4; q++) acc[mf][g][hh][q] = 0.f;
#pragma unroll
            for (int kc = 0; kc < 8; kc++) {
                uint4 a[2];
#pragma unroll
                for (int mf = 0; mf < 2; mf++)
                    a[mf] = ((const uint4*)sA)[((wm * 2 + mf) * 8 + kc) * 32 + lane];
#pragma unroll
                for (int g = 0; g < 4; g++)
#pragma unroll
                    for (int hh = 0; hh < 2; hh++) {
                        int n8 = g * 8 + wn * 2 + hh;
                        uint2 b = ((const uint2*)sW)[(kc * 32 + n8) * 32 + lane];
#pragma unroll
                        for (int mf = 0; mf < 2; mf++)
                            mma16(acc[mf][g][hh], a[mf], b);
                    }
            }
#pragma unroll
            for (int mf = 0; mf < 2; mf++)
#pragma unroll
                for (int rr = 0; rr < 2; rr++) {
                    int m = m0 + wm * 32 + mf * 16 + gid + rr * 8;
#pragma unroll
                    for (int g = 0; g < 4; g++)
#pragma unroll
                        for (int hh = 0; hh < 2; hh++) {
                            int n0 = g * 64 + wn * 16 + hh * 8 + tig * 2;
                            float2 bv = *(const float2*)&bias[n0];
                            float vx = acc[mf][g][hh][rr * 2 + 0] + bv.x;
                            float vy = acc[mf][g][hh][rr * 2 + 1] + bv.y;
                            preh[(size_t)m * 128 + (n0 >> 1)] = h2u(vx, vy);
                        }
                }
        }
    }
}

// ---------------- persistent fused LSTM chain (32-row tiles, MLP-8 gather) --------
#define CHAIN_SMEM (160 * 1024)
__global__ __launch_bounds__(512, 1) void k_chain(const float* __restrict__ Wr1,
                                                  const float* __restrict__ Wroot1,
                                                  const float* __restrict__ Wr2,
                                                  const float* __restrict__ Wroot2,
                                                  float* __restrict__ outC2) {
    extern __shared__ unsigned smem[];
    unsigned* sW = smem;                      // 16384 u32
    unsigned* sA = smem + 8 * 32 * 32 * 2;    // 2048 u32 (32-row tile)
    int tid = threadIdx.x;
    int warp = tid >> 5, lane = tid & 31;
    int wm = warp >> 3, wn = warp & 7;        // 2 x 8 warps over 32x256 tile
    int gid = lane >> 2, tig = lane & 3;
    unsigned gen = g_bar_gen;

    for (int i = blockIdx.x * 512 + tid; i < NN * 32; i += gridDim.x * 512)
        g_hh[0][i] = 0u;
    for (int i = blockIdx.x * 512 + tid; i < NN * HH; i += gridDim.x * 512)
        g_c[i] = 0.f;
    gridbar(gen);

    int par = 0;
    for (int L = 0; L < 2; L++) {
        const float* __restrict__ Wr = L ? Wr2 : Wr1;
        const float* __restrict__ Wroot = L ? Wroot2 : Wroot1;
        for (int i = tid; i < 64 * 256; i += 512) {
            int k2 = i >> 8, n = i & 255;
            int k = k2 * 2;
            float v0, v1;
            if (k < 64) {
                v0 = Wr[(size_t)(64 + k) * 256 + n];
                v1 = Wr[(size_t)(65 + k) * 256 + n];
            } else {
                v0 = Wroot[(size_t)k * 256 + n];
                v1 = Wroot[(size_t)(k + 1) * 256 + n];
            }
            int kc = k2 >> 3, breg = (k2 >> 2) & 1;
            int bl = (n & 7) * 4 + (k2 & 3);
            sW[((kc * 32 + (n >> 3)) * 32 + bl) * 2 + breg] = h2u(v0, v1);
        }
        __syncthreads();
        const unsigned* __restrict__ preL = g_preh[L];

        for (int t = 0; t < TT; t++) {
            const unsigned* __restrict__ hin = g_hh[par];
            unsigned* __restrict__ hout = g_hh[par ^ 1];
            const unsigned* __restrict__ pre = preL + (size_t)t * NN * 128;
            int store = (L == 1 && t >= TT - 4) ? (t - (TT - 4)) : -1;

            for (int tile = blockIdx.x; tile < N_TILES; tile += gridDim.x) {
                int m0 = tile * 32;
                __syncthreads();
                // gather: 16 warps x 2 rows; lane = feature pair
#pragma unroll
                for (int rq = 0; rq < 2; rq++) {
                    int r = warp * 2 + rq;
                    int m = m0 + r;
                    int e0 = g_rowptr[m], e1 = g_rowptr[m + 1];
                    float ax = 0.f, ay = 0.f;
                    for (int e = e0; e < e1; e += 8) {
                        int idx[8];
                        float wv[8];
                        unsigned uv[8];
#pragma unroll
                        for (int j = 0; j < 8; j++) {
                            int p = e + j;
                            int pc = (p < e1) ? p : (e1 - 1);
                            idx[j] = __ldg(&g_csr_src[pc]);
                            wv[j] = (p < e1) ? __ldg(&g_csr_w[pc]) : 0.f;
                        }
#pragma unroll
                        for (int j = 0; j < 8; j++)
                            uv[j] = __ldg(&hin[(size_t)idx[j] * 32 + lane]);
#pragma unroll
                        for (int j = 0; j < 8; j++) {
                            float2 v = u2f2(uv[j]);
                            ax += wv[j] * v.x;
                            ay += wv[j] * v.y;
                        }
                    }
                    float inv = 1.f / (float)max(e1 - e0, 1);
                    unsigned aggu = h2u(ax * inv, ay * inv);
                    unsigned hu = hin[(size_t)m * 32 + lane];
                    int mf = r >> 4;
                    int al = (r & 7) * 4 + (lane & 3);
                    int regc = ((lane >> 2) & 1) * 2 + ((r >> 3) & 1);
                    int kcA = lane >> 3;
                    sA[((mf * 8 + kcA) * 32 + al) * 4 + regc] = aggu;
                    sA[((mf * 8 + 4 + kcA) * 32 + al) * 4 + regc] = hu;
                }
                __syncthreads();
                float acc[4][4];
#pragma unroll
                for (int g = 0; g < 4; g++)
#pragma unroll
                    for (int q = 0; q < 4; q++) acc[g][q] = 0.f;
#pragma unroll
                for (int kc = 0; kc < 8; kc++) {
                    uint4 a = ((const uint4*)sA)[(wm * 8 + kc) * 32 + lane];
#pragma unroll
                    for (int g = 0; g < 4; g++) {
                        int n8 = g * 8 + wn;
                        uint2 b = ((const uint2*)sW)[(kc * 32 + n8) * 32 + lane];
                        mma16(acc[g], a, b);
                    }
                }
#pragma unroll
                for (int rr = 0; rr < 2; rr++) {
                    int m = m0 + wm * 16 + gid + rr * 8;
                    int hc = wn * 8 + tig * 2;
                    size_t pb = (size_t)m * 128 + (hc >> 1);
                    float2 pi = u2f2(pre[pb]);
                    float2 pf = u2f2(pre[pb + 32]);
                    float2 pg = u2f2(pre[pb + 64]);
                    float2 po = u2f2(pre[pb + 96]);
                    size_t hb = (size_t)m * 64 + hc;
                    float2 cold = *(const float2*)&g_c[hb];
                    float gi0 = acc[0][rr * 2 + 0] + pi.x;
                    float gi1 = acc[0][rr * 2 + 1] + pi.y;
                    float gf0 = acc[1][rr * 2 + 0] + pf.x;
                    float gf1 = acc[1][rr * 2 + 1] + pf.y;
                    float gg0 = acc[2][rr * 2 + 0] + pg.x;
                    float gg1 = acc[2][rr * 2 + 1] + pg.y;
                    float go0 = acc[3][rr * 2 + 0] + po.x;
                    float go1 = acc[3][rr * 2 + 1] + po.y;
                    float si0 = __fdividef(1.f, 1.f + __expf(-gi0));
                    float si1 = __fdividef(1.f, 1.f + __expf(-gi1));
                    float sf0 = __fdividef(1.f, 1.f + __expf(-gf0));
                    float sf1 = __fdividef(1.f, 1.f + __expf(-gf1));
                    float so0 = __fdividef(1.f, 1.f + __expf(-go0));
                    float so1 = __fdividef(1.f, 1.f + __expf(-go1));
                    float2 cn, hn;
                    cn.x = sf0 * cold.x + si0 * tanhf(gg0);
                    cn.y = sf1 * cold.y + si1 * tanhf(gg1);
                    hn.x = so0 * tanhf(cn.x);
                    hn.y = so1 * tanhf(cn.y);
                    *(float2*)&g_c[hb] = cn;
                    hout[(size_t)m * 32 + (hc >> 1)] = h2u(hn.x, hn.y);
                    if (store >= 0)
                        *(float2*)&g_h2last[(size_t)store * NN * 64 + hb] = hn;
                }
            }
            gridbar(gen);
            par ^= 1;
        }
        __syncthreads();
    }

    for (int i = blockIdx.x * 512 + tid; i < NN * HH; i += gridDim.x * 512)
        outC2[i] = g_c[i];
}

// ---------------- final projection: out = [relu(emb), h2][-4:] @ W_out + b_out ----
__global__ __launch_bounds__(256) void k_out(const float* __restrict__ emb,
                                             const float* __restrict__ Wout,
                                             const float* __restrict__ bout,
                                             float* __restrict__ out) {
    __shared__ float sX[32][129];
    __shared__ float sW[128][9];
    int tt = blockIdx.y;
    int n0 = blockIdx.x * 32;
    int tid = threadIdx.x;
    for (int i = tid; i < 32 * 64; i += 256) {
        int r = i >> 6, k = i & 63;
        int m = n0 + r;
        sX[r][k] = (m < NN)
            ? fmaxf(emb[((size_t)(TT - 4 + tt) * NN + m) * 64 + k], 0.f) : 0.f;
        sX[r][64 + k] = (m < NN) ? g_h2last[((size_t)tt * NN + m) * 64 + k] : 0.f;
    }
    for (int i = tid; i < 128 * 8; i += 256) sW[i >> 3][i & 7] = Wout[i];
    __syncthreads();
    int node = tid >> 3, o = tid & 7;
    float acc = bout[o];
    for (int k = 0; k < 128; k++) acc += sX[node][k] * sW[k][o];
    int m = n0 + node;
    if (m < NN) out[((size_t)tt * NN + m) * 8 + o] = acc;
}

// ---------------- launch ----------------------------------------------------------
extern "C" void kernel_launch(void* const* d_in, const int* in_sizes, int n_in,
                              void* d_out, int out_size) {
    const float* x      = (const float*)d_in[0];
    const int*   ei     = (const int*)d_in[1];
    const float* ew     = (const float*)d_in[2];
    const float* sWr    = (const float*)d_in[3];
    const float* sWroot = (const float*)d_in[4];
    const float* sb     = (const float*)d_in[5];
    const float* Wr1    = (const float*)d_in[6];
    const float* Wroot1 = (const float*)d_in[7];
    const float* b1     = (const float*)d_in[8];
    const float* Wr2    = (const float*)d_in[9];
    const float* Wroot2 = (const float*)d_in[10];
    const float* b2     = (const float*)d_in[11];
    const float* Wout   = (const float*)d_in[12];
    const float* bout   = (const float*)d_in[13];
    float* out = (float*)d_out;
    const int* src = ei;
    const int* dst = ei + EE;

    int nsm = 0;
    cudaDeviceGetAttribute(&nsm, cudaDevAttrMultiProcessorCount, 0);
    cudaFuncSetAttribute(k_chain, cudaFuncAttributeMaxDynamicSharedMemorySize,
                         CHAIN_SMEM);
    cudaFuncSetAttribute(k_pre, cudaFuncAttributeMaxDynamicSharedMemorySize,
                         PRE_SMEM);

    // [1] CSR build (persistent, grid-barriered)
    k_csr<<<nsm, 256>>>(src, dst, ew);
    // [2] SAGE embedding with fused aggregation (exact fp32 -> emb; fp16 xr)
    k_sage<<<TT * NN / 64, 256>>>(x, sWr, sWroot, sb, out + EMB_OFF);
    // [3] gate pre-contributions with fused wmean(xr) gather (fp16, persistent)
    k_pre<<<nsm, 512, PRE_SMEM>>>(Wr1, Wroot1, b1, Wr2, Wroot2, b2);
    // [4] fused persistent LSTM chain (profiled slot)
    k_chain<<<nsm, 512, CHAIN_SMEM>>>(Wr1, Wroot1, Wr2, Wroot2, out + C2_OFF);
    // [5] output projection
    k_out<<<dim3(NN / 32, 4), 256>>>(out + EMB_OFF, Wout, bout, out + OUT_OFF);
}

// round 10
// speedup vs baseline: 1.1821x; 1.1821x over previous
#include <cuda_runtime.h>
#include <cuda_fp16.h>
#include <math.h>

#define TT 12
#define NN 20000
#define EE 400000
#define FF 32
#define HH 64
#define OO 8

// Output layout (flattened tuple): out[4,N,8] | c2[N,64] | emb[T,N,64]
#define OUT_OFF 0
#define C2_OFF  (4*NN*OO)                 // 640000
#define EMB_OFF (C2_OFF + NN*HH)          // 1920000

#define CH_TILES ((NN + 31) / 32)         // 625 chain tiles (32 rows)
#define PRE_TILES (TT * NN / 128)         // 1875

// ---------------- scratch (static device globals; allocation-free at runtime) ----
__device__ int      g_rowptr[NN + 1];
__device__ int      g_cursor[NN];
__device__ int      g_csr_src[EE];
__device__ float    g_csr_w[EE];
__device__ unsigned g_xrh[TT * NN * 32];         // relu(emb) as half2 pairs
__device__ float    g_aggx[TT * NN * FF];        // wmean(x) per t (fp32, emb path)
__device__ unsigned g_aggxrh[TT * NN * 32];      // wmean(xr) as half2 pairs
__device__ unsigned g_preh[2][TT * NN * 128];    // gate pre-contrib, half2 pairs
__device__ unsigned g_hh[2][NN * 32];            // fp16 hidden state (half2 words)
__device__ float    g_c[NN * HH];
__device__ float    g_h2last[4 * NN * HH];       // h2 for last 4 steps (fp32)
__device__ int      g_ctr[2 * TT];               // per-step tile tickets

// grid barrier state
__device__ unsigned g_bar_count = 0;
__device__ volatile unsigned g_bar_gen = 0;

// ---------------- helpers ----------------------------------------------------------
__device__ __forceinline__ void mma16(float* c, const uint4 a, const uint2 b) {
    asm volatile(
        "mma.sync.aligned.m16n8k16.row.col.f32.f16.f16.f32 "
        "{%0,%1,%2,%3},{%4,%5,%6,%7},{%8,%9},{%0,%1,%2,%3};"
        : "+f"(c[0]), "+f"(c[1]), "+f"(c[2]), "+f"(c[3])
        : "r"(a.x), "r"(a.y), "r"(a.z), "r"(a.w), "r"(b.x), "r"(b.y));
}
__device__ __forceinline__ unsigned h2u(float lo, float hi) {
    __half2 h = __floats2half2_rn(lo, hi);
    return *(unsigned*)&h;
}
__device__ __forceinline__ float2 u2f2(unsigned u) {
    return __half22float2(*(const __half2*)&u);
}
__device__ __forceinline__ unsigned long long pk2(float lo, float hi) {
    unsigned long long r;
    asm("mov.b64 %0, {%1,%2};" : "=l"(r) : "f"(lo), "f"(hi));
    return r;
}
__device__ __forceinline__ void upk2(unsigned long long v, float& lo, float& hi) {
    asm("mov.b64 {%0,%1}, %2;" : "=f"(lo), "=f"(hi) : "l"(v));
}
__device__ __forceinline__ unsigned long long ffma2(unsigned long long a,
                                                    unsigned long long b,
                                                    unsigned long long c) {
    unsigned long long d;
    asm("fma.rn.f32x2 %0, %1, %2, %3;" : "=l"(d) : "l"(a), "l"(b), "l"(c));
    return d;
}
__device__ __forceinline__ unsigned ld_acq(volatile unsigned* p) {
    unsigned v;
    asm volatile("ld.acquire.gpu.u32 %0, [%1];"
                 : "=r"(v) : "l"((const unsigned*)p) : "memory");
    return v;
}
__device__ __forceinline__ void gridbar(unsigned& gen) {
    __syncthreads();
    if (threadIdx.x == 0) {
        __threadfence();
        unsigned t = atomicAdd(&g_bar_count, 1);
        if (t == gridDim.x - 1) {
            g_bar_count = 0;
            __threadfence();
            asm volatile("st.release.gpu.u32 [%0], %1;"
                         :: "l"((unsigned*)&g_bar_gen), "r"(gen + 1) : "memory");
        } else {
            while (ld_acq(&g_bar_gen) != gen + 1) __nanosleep(16);
        }
    }
    gen++;
    __syncthreads();
}

// ---------------- CSR construction (separate launches; proven fast) ---------------
__global__ void k_zero_cursor() {
    int i = blockIdx.x * blockDim.x + threadIdx.x;
    if (i < NN) g_cursor[i] = 0;
}

__global__ void k_deg(const int* __restrict__ dst) {
    int e = blockIdx.x * blockDim.x + threadIdx.x;
    if (e < EE) atomicAdd(&g_cursor[dst[e]], 1);
}

__global__ void k_scan() {
    __shared__ int wsum[32];
    const int CH = 20;
    int tid = threadIdx.x;
    int base = tid * CH;
    int loc[CH];
    int s = 0;
#pragma unroll
    for (int i = 0; i < CH; i++) {
        int idx = base + i;
        int v = (idx < NN) ? g_cursor[idx] : 0;
        loc[i] = s;
        s += v;
    }
    int lane = tid & 31, w = tid >> 5;
    int inc = s;
#pragma unroll
    for (int o = 1; o < 32; o <<= 1) {
        int t = __shfl_up_sync(0xffffffffu, inc, o);
        if (lane >= o) inc += t;
    }
    if (lane == 31) wsum[w] = inc;
    __syncthreads();
    if (w == 0) {
        int v = wsum[lane];
#pragma unroll
        for (int o = 1; o < 32; o <<= 1) {
            int t = __shfl_up_sync(0xffffffffu, v, o);
            if (lane >= o) v += t;
        }
        wsum[lane] = v;
    }
    __syncthreads();
    int excl = inc - s + (w > 0 ? wsum[w - 1] : 0);
#pragma unroll
    for (int i = 0; i < CH; i++) {
        int idx = base + i;
        if (idx < NN) {
            int p = excl + loc[i];
            g_rowptr[idx] = p;
            g_cursor[idx] = p;
        }
    }
    if (tid == 0) g_rowptr[NN] = EE;
}

__global__ void k_fill(const int* __restrict__ src, const int* __restrict__ dst,
                       const float* __restrict__ ew) {
    int e = blockIdx.x * blockDim.x + threadIdx.x;
    if (e < EE) {
        int d = dst[e];
        int pos = atomicAdd(&g_cursor[d], 1);
        g_csr_src[pos] = src[e];
        g_csr_w[pos] = ew[e];
    }
}

// ---------------- wmean of x (fp32, emb path), MLP-4 edge loop, parallel T --------
__global__ void k_aggx(const float* __restrict__ xin) {
    int gw = (blockIdx.x * blockDim.x + threadIdx.x) >> 5;
    int lane = threadIdx.x & 31;
    if (gw >= NN) return;
    size_t toff = (size_t)blockIdx.y * NN * FF;
    const float* __restrict__ in = xin + toff;
    float* __restrict__ out = g_aggx + toff;

    int e0 = g_rowptr[gw], e1 = g_rowptr[gw + 1];
    float acc = 0.f;
    int e = e0;
    for (; e + 4 <= e1; e += 4) {
        int s0 = __ldg(&g_csr_src[e]);
        int s1 = __ldg(&g_csr_src[e + 1]);
        int s2 = __ldg(&g_csr_src[e + 2]);
        int s3 = __ldg(&g_csr_src[e + 3]);
        float w0 = __ldg(&g_csr_w[e]);
        float w1 = __ldg(&g_csr_w[e + 1]);
        float w2 = __ldg(&g_csr_w[e + 2]);
        float w3 = __ldg(&g_csr_w[e + 3]);
        float v0 = __ldg(&in[(size_t)s0 * FF + lane]);
        float v1 = __ldg(&in[(size_t)s1 * FF + lane]);
        float v2 = __ldg(&in[(size_t)s2 * FF + lane]);
        float v3 = __ldg(&in[(size_t)s3 * FF + lane]);
        acc += w0 * v0 + w1 * v1 + w2 * v2 + w3 * v3;
    }
    for (; e < e1; e++) {
        int s = __ldg(&g_csr_src[e]);
        float w = __ldg(&g_csr_w[e]);
        acc += w * __ldg(&in[(size_t)s * FF + lane]);
    }
    out[(size_t)gw * FF + lane] = acc / (float)max(e1 - e0, 1);
}

// ---------------- wmean of xr (fp16 in/out), MLP-4, parallel T --------------------
__global__ void k_aggh() {
    int gw = (blockIdx.x * blockDim.x + threadIdx.x) >> 5;
    int lane = threadIdx.x & 31;
    if (gw >= NN) return;
    size_t toff = (size_t)blockIdx.y * NN * 32;
    const unsigned* __restrict__ in = g_xrh + toff;
    unsigned* __restrict__ out = g_aggxrh + toff;

    int e0 = g_rowptr[gw], e1 = g_rowptr[gw + 1];
    float ax = 0.f, ay = 0.f;
    int e = e0;
    for (; e + 4 <= e1; e += 4) {
        int s0 = __ldg(&g_csr_src[e]);
        int s1 = __ldg(&g_csr_src[e + 1]);
        int s2 = __ldg(&g_csr_src[e + 2]);
        int s3 = __ldg(&g_csr_src[e + 3]);
        float w0 = __ldg(&g_csr_w[e]);
        float w1 = __ldg(&g_csr_w[e + 1]);
        float w2 = __ldg(&g_csr_w[e + 2]);
        float w3 = __ldg(&g_csr_w[e + 3]);
        float2 v0 = u2f2(__ldg(&in[(size_t)s0 * 32 + lane]));
        float2 v1 = u2f2(__ldg(&in[(size_t)s1 * 32 + lane]));
        float2 v2 = u2f2(__ldg(&in[(size_t)s2 * 32 + lane]));
        float2 v3 = u2f2(__ldg(&in[(size_t)s3 * 32 + lane]));
        ax += w0 * v0.x + w1 * v1.x + w2 * v2.x + w3 * v3.x;
        ay += w0 * v0.y + w1 * v1.y + w2 * v2.y + w3 * v3.y;
    }
    for (; e < e1; e++) {
        int s = __ldg(&g_csr_src[e]);
        float w = __ldg(&g_csr_w[e]);
        float2 v = u2f2(__ldg(&in[(size_t)s * 32 + lane]));
        ax += w * v.x;
        ay += w * v.y;
    }
    float inv = 1.f / (float)max(e1 - e0, 1);
    out[(size_t)gw * 32 + lane] = h2u(ax * inv, ay * inv);
}

// ---------------- SAGE (f32x2 core, exact fp32): emb fp32; xrh fp16 ---------------
__global__ __launch_bounds__(256, 2) void k_sage(const float* __restrict__ x,
                                                 const float* __restrict__ Wr,
                                                 const float* __restrict__ Wroot,
                                                 const float* __restrict__ b,
                                                 float* __restrict__ emb) {
    __shared__ float sA[64][33];
    __shared__ float sW[32][66];
    int m0 = blockIdx.x * 64;
    int tid = threadIdx.x;
    int tr = tid / 16, tc = tid % 16;
    unsigned long long acc[4][2];
#pragma unroll
    for (int i = 0; i < 4; i++)
#pragma unroll
        for (int j2 = 0; j2 < 2; j2++) acc[i][j2] = 0ull;
    for (int kb = 0; kb < 2; kb++) {
        const float* Asrc = kb ? x : g_aggx;
        const float* Wsrc = kb ? Wroot : Wr;
        __syncthreads();
        for (int i = tid; i < 64 * 32; i += 256) {
            int r = i >> 5, k = i & 31;
            sA[r][k] = Asrc[(size_t)(m0 + r) * 32 + k];
        }
        for (int i = tid; i < 32 * 64; i += 256) {
            int r = i >> 6, cc = i & 63;
            sW[r][cc] = Wsrc[(size_t)r * 64 + cc];
        }
        __syncthreads();
#pragma unroll
        for (int k = 0; k < 32; k++) {
            unsigned long long a2[4];
#pragma unroll
            for (int i = 0; i < 4; i++) {
                float av = sA[tr * 4 + i][k];
                a2[i] = pk2(av, av);
            }
#pragma unroll
            for (int j2 = 0; j2 < 2; j2++) {
                unsigned long long w2 = *(const unsigned long long*)&sW[k][tc * 4 + j2 * 2];
#pragma unroll
                for (int i = 0; i < 4; i++) acc[i][j2] = ffma2(a2[i], w2, acc[i][j2]);
            }
        }
    }
#pragma unroll
    for (int i = 0; i < 4; i++) {
        int m = m0 + tr * 4 + i;
        size_t mrow = (size_t)m * 64;
#pragma unroll
        for (int j2 = 0; j2 < 2; j2++) {
            float v0, v1;
            upk2(acc[i][j2], v0, v1);
            int c0 = tc * 4 + j2 * 2;
            v0 += b[c0];
            v1 += b[c0 + 1];
            emb[mrow + c0] = v0;
            emb[mrow + c0 + 1] = v1;
            g_xrh[(size_t)m * 32 + (c0 >> 1)] = h2u(fmaxf(v0, 0.f), fmaxf(v1, 0.f));
        }
    }
}

// ---------------- persistent PRE (fp16 mma): both layers, W staged once/SM --------
#define PRE_SMEM ((8 * 32 * 32 * 2 + 8 * 8 * 32 * 4) * 4)
__global__ __launch_bounds__(512, 1) void k_pre(const float* __restrict__ Wr1,
                                                const float* __restrict__ Wroot1,
                                                const float* __restrict__ b1,
                                                const float* __restrict__ Wr2,
                                                const float* __restrict__ Wroot2,
                                                const float* __restrict__ b2) {
    extern __shared__ unsigned smem[];
    unsigned* sW = smem;
    unsigned* sA = smem + 8 * 32 * 32 * 2;
    int tid = threadIdx.x;
    int warp = tid >> 5, lane = tid & 31;
    int wm = warp >> 2, wn = warp & 3;
    int gid = lane >> 2, tig = lane & 3;

    for (int L = 0; L < 2; L++) {
        const float* __restrict__ Wr = L ? Wr2 : Wr1;
        const float* __restrict__ Wroot = L ? Wroot2 : Wroot1;
        const float* __restrict__ bias = L ? b2 : b1;
        unsigned* __restrict__ preh = g_preh[L];
        __syncthreads();
        for (int i = tid; i < 64 * 256; i += 512) {
            int k2 = i >> 8, n = i & 255;
            int k = k2 * 2;
            float v0, v1;
            if (k < 64) {
                v0 = Wr[(size_t)k * 256 + n];
                v1 = Wr[(size_t)(k + 1) * 256 + n];
            } else {
                v0 = Wroot[(size_t)(k - 64) * 256 + n];
                v1 = Wroot[(size_t)(k - 63) * 256 + n];
            }
            int kc = k2 >> 3, breg = (k2 >> 2) & 1;
            int bl = (n & 7) * 4 + (k2 & 3);
            sW[((kc * 32 + (n >> 3)) * 32 + bl) * 2 + breg] = h2u(v0, v1);
        }
        __syncthreads();

        for (int tile = blockIdx.x; tile < PRE_TILES; tile += gridDim.x) {
            int m0 = tile * 128;
            __syncthreads();
            for (int i = tid; i < 128 * 64; i += 512) {
                int r = i >> 6, c2 = i & 63;
                size_t m32 = (size_t)(m0 + r) * 32;
                unsigned u = (c2 < 32) ? g_aggxrh[m32 + c2] : g_xrh[m32 + (c2 - 32)];
                int mf = r >> 4, kc = c2 >> 3;
                int reg = ((c2 >> 2) & 1) * 2 + ((r >> 3) & 1);
                int al = (r & 7) * 4 + (c2 & 3);
                sA[((mf * 8 + kc) * 32 + al) * 4 + reg] = u;
            }
            __syncthreads();
            float acc[2][4][2][4];
#pragma unroll
            for (int mf = 0; mf < 2; mf++)
#pragma unroll
                for (int g = 0; g < 4; g++)
#pragma unroll
                    for (int hh = 0; hh < 2; hh++)
#pragma unroll
                        for (int q = 0; q < 4; q++) acc[mf][g][hh][q] = 0.f;
#pragma unroll
            for (int kc = 0; kc < 8; kc++) {
                uint4 a[2];
#pragma unroll
                for (int mf = 0; mf < 2; mf++)
                    a[mf] = ((const uint4*)sA)[((wm * 2 + mf) * 8 + kc) * 32 + lane];
#pragma unroll
                for (int g = 0; g < 4; g++)
#pragma unroll
                    for (int hh = 0; hh < 2; hh++) {
                        int n8 = g * 8 + wn * 2 + hh;
                        uint2 b = ((const uint2*)sW)[(kc * 32 + n8) * 32 + lane];
#pragma unroll
                        for (int mf = 0; mf < 2; mf++)
                            mma16(acc[mf][g][hh], a[mf], b);
                    }
            }
#pragma unroll
            for (int mf = 0; mf < 2; mf++)
#pragma unroll
                for (int rr = 0; rr < 2; rr++) {
                    int m = m0 + wm * 32 + mf * 16 + gid + rr * 8;
#pragma unroll
                    for (int g = 0; g < 4; g++)
#pragma unroll
                        for (int hh = 0; hh < 2; hh++) {
                            int n0 = g * 64 + wn * 16 + hh * 8 + tig * 2;
                            float2 bv = *(const float2*)&bias[n0];
                            float vx = acc[mf][g][hh][rr * 2 + 0] + bv.x;
                            float vy = acc[mf][g][hh][rr * 2 + 1] + bv.y;
                            preh[(size_t)m * 128 + (n0 >> 1)] = h2u(vx, vy);
                        }
                }
        }
    }
}

// ---------------- persistent fused LSTM chain: 32-row tiles, ticket stealing ------
#define CHAIN_SMEM (160 * 1024)
__global__ __launch_bounds__(512, 1) void k_chain(const float* __restrict__ Wr1,
                                                  const float* __restrict__ Wroot1,
                                                  const float* __restrict__ Wr2,
                                                  const float* __restrict__ Wroot2,
                                                  float* __restrict__ outC2) {
    extern __shared__ unsigned smem[];
    unsigned* sW = smem;                      // 16384 u32
    unsigned* sA = smem + 8 * 32 * 32 * 2;    // 2048 u32 (32-row tile)
    __shared__ int sTicket;
    int tid = threadIdx.x;
    int warp = tid >> 5, lane = tid & 31;
    int wm = warp >> 3, wn = warp & 7;        // 2 x 8 warps over 32x256 tile
    int gid = lane >> 2, tig = lane & 3;
    unsigned gen = g_bar_gen;

    // init h0, c0, per-step tickets
    for (int i = blockIdx.x * 512 + tid; i < NN * 32; i += gridDim.x * 512)
        g_hh[0][i] = 0u;
    for (int i = blockIdx.x * 512 + tid; i < NN * HH; i += gridDim.x * 512)
        g_c[i] = 0.f;
    if (blockIdx.x == 0 && tid < 2 * TT) g_ctr[tid] = 0;
    gridbar(gen);

    int par = 0;
    for (int L = 0; L < 2; L++) {
        const float* __restrict__ Wr = L ? Wr2 : Wr1;
        const float* __restrict__ Wroot = L ? Wroot2 : Wroot1;
        for (int i = tid; i < 64 * 256; i += 512) {
            int k2 = i >> 8, n = i & 255;
            int k = k2 * 2;
            float v0, v1;
            if (k < 64) {
                v0 = Wr[(size_t)(64 + k) * 256 + n];
                v1 = Wr[(size_t)(65 + k) * 256 + n];
            } else {
                v0 = Wroot[(size_t)k * 256 + n];
                v1 = Wroot[(size_t)(k + 1) * 256 + n];
            }
            int kc = k2 >> 3, breg = (k2 >> 2) & 1;
            int bl = (n & 7) * 4 + (k2 & 3);
            sW[((kc * 32 + (n >> 3)) * 32 + bl) * 2 + breg] = h2u(v0, v1);
        }
        __syncthreads();
        const unsigned* __restrict__ preL = g_preh[L];

        for (int t = 0; t < TT; t++) {
            const unsigned* __restrict__ hin = g_hh[par];
            unsigned* __restrict__ hout = g_hh[par ^ 1];
            const unsigned* __restrict__ pre = preL + (size_t)t * NN * 128;
            int store = (L == 1 && t >= TT - 4) ? (t - (TT - 4)) : -1;
            int step_id = L * TT + t;

            for (;;) {
                __syncthreads();   // previous tile fully consumed before re-staging
                if (tid == 0) sTicket = atomicAdd(&g_ctr[step_id], 1);
                __syncthreads();
                int tile = sTicket;
                if (tile >= CH_TILES) break;
                int m0 = tile * 32;

                // gather: 16 warps x 2 rows; lane = feature pair (MLP-4 + tail)
#pragma unroll
                for (int rq = 0; rq < 2; rq++) {
                    int r = warp * 2 + rq;
                    int m = m0 + r;
                    unsigned aggu = 0u, hu = 0u;
                    if (m < NN) {
                        int e0 = g_rowptr[m], e1 = g_rowptr[m + 1];
                        float ax = 0.f, ay = 0.f;
                        int e = e0;
                        for (; e + 4 <= e1; e += 4) {
                            int s0 = __ldg(&g_csr_src[e]);
                            int s1 = __ldg(&g_csr_src[e + 1]);
                            int s2 = __ldg(&g_csr_src[e + 2]);
                            int s3 = __ldg(&g_csr_src[e + 3]);
                            float w0 = __ldg(&g_csr_w[e]);
                            float w1 = __ldg(&g_csr_w[e + 1]);
                            float w2 = __ldg(&g_csr_w[e + 2]);
                            float w3 = __ldg(&g_csr_w[e + 3]);
                            float2 v0 = u2f2(__ldg(&hin[(size_t)s0 * 32 + lane]));
                            float2 v1 = u2f2(__ldg(&hin[(size_t)s1 * 32 + lane]));
                            float2 v2 = u2f2(__ldg(&hin[(size_t)s2 * 32 + lane]));
                            float2 v3 = u2f2(__ldg(&hin[(size_t)s3 * 32 + lane]));
                            ax += w0 * v0.x + w1 * v1.x + w2 * v2.x + w3 * v3.x;
                            ay += w0 * v0.y + w1 * v1.y + w2 * v2.y + w3 * v3.y;
                        }
                        for (; e < e1; e++) {
                            int s = __ldg(&g_csr_src[e]);
                            float w = __ldg(&g_csr_w[e]);
                            float2 v = u2f2(__ldg(&hin[(size_t)s * 32 + lane]));
                            ax += w * v.x;
                            ay += w * v.y;
                        }
                        float inv = 1.f / (float)max(e1 - e0, 1);
                        aggu = h2u(ax * inv, ay * inv);
                        hu = hin[(size_t)m * 32 + lane];
                    }
                    int mf = r >> 4;
                    int al = (r & 7) * 4 + (lane & 3);
                    int regc = ((lane >> 2) & 1) * 2 + ((r >> 3) & 1);
                    int kcA = lane >> 3;
                    sA[((mf * 8 + kcA) * 32 + al) * 4 + regc] = aggu;
                    sA[((mf * 8 + 4 + kcA) * 32 + al) * 4 + regc] = hu;
                }
                __syncthreads();
                float acc[4][4];
#pragma unroll
                for (int g = 0; g < 4; g++)
#pragma unroll
                    for (int q = 0; q < 4; q++) acc[g][q] = 0.f;
#pragma unroll
                for (int kc = 0; kc < 8; kc++) {
                    uint4 a = ((const uint4*)sA)[(wm * 8 + kc) * 32 + lane];
#pragma unroll
                    for (int g = 0; g < 4; g++) {
                        int n8 = g * 8 + wn;
                        uint2 b = ((const uint2*)sW)[(kc * 32 + n8) * 32 + lane];
                        mma16(acc[g], a, b);
                    }
                }
#pragma unroll
                for (int rr = 0; rr < 2; rr++) {
                    int m = m0 + wm * 16 + gid + rr * 8;
                    if (m >= NN) continue;
                    int hc = wn * 8 + tig * 2;
                    size_t pb = (size_t)m * 128 + (hc >> 1);
                    float2 pi = u2f2(pre[pb]);
                    float2 pf = u2f2(pre[pb + 32]);
                    float2 pg = u2f2(pre[pb + 64]);
                    float2 po = u2f2(pre[pb + 96]);
                    size_t hb = (size_t)m * 64 + hc;
                    float2 cold = *(const float2*)&g_c[hb];
                    float gi0 = acc[0][rr * 2 + 0] + pi.x;
                    float gi1 = acc[0][rr * 2 + 1] + pi.y;
                    float gf0 = acc[1][rr * 2 + 0] + pf.x;
                    float gf1 = acc[1][rr * 2 + 1] + pf.y;
                    float gg0 = acc[2][rr * 2 + 0] + pg.x;
                    float gg1 = acc[2][rr * 2 + 1] + pg.y;
                    float go0 = acc[3][rr * 2 + 0] + po.x;
                    float go1 = acc[3][rr * 2 + 1] + po.y;
                    float si0 = __fdividef(1.f, 1.f + __expf(-gi0));
                    float si1 = __fdividef(1.f, 1.f + __expf(-gi1));
                    float sf0 = __fdividef(1.f, 1.f + __expf(-gf0));
                    float sf1 = __fdividef(1.f, 1.f + __expf(-gf1));
                    float so0 = __fdividef(1.f, 1.f + __expf(-go0));
                    float so1 = __fdividef(1.f, 1.f + __expf(-go1));
                    float2 cn, hn;
                    cn.x = sf0 * cold.x + si0 * tanhf(gg0);
                    cn.y = sf1 * cold.y + si1 * tanhf(gg1);
                    hn.x = so0 * tanhf(cn.x);
                    hn.y = so1 * tanhf(cn.y);
                    *(float2*)&g_c[hb] = cn;
                    hout[(size_t)m * 32 + (hc >> 1)] = h2u(hn.x, hn.y);
                    if (store >= 0)
                        *(float2*)&g_h2last[(size_t)store * NN * 64 + hb] = hn;
                }
            }
            gridbar(gen);
            par ^= 1;
        }
        __syncthreads();
    }

    for (int i = blockIdx.x * 512 + tid; i < NN * HH; i += gridDim.x * 512)
        outC2[i] = g_c[i];
}

// ---------------- final projection: out = [relu(emb), h2][-4:] @ W_out + b_out ----
__global__ __launch_bounds__(256) void k_out(const float* __restrict__ emb,
                                             const float* __restrict__ Wout,
                                             const float* __restrict__ bout,
                                             float* __restrict__ out) {
    __shared__ float sX[32][129];
    __shared__ float sW[128][9];
    int tt = blockIdx.y;
    int n0 = blockIdx.x * 32;
    int tid = threadIdx.x;
    for (int i = tid; i < 32 * 64; i += 256) {
        int r = i >> 6, k = i & 63;
        int m = n0 + r;
        sX[r][k] = (m < NN)
            ? fmaxf(emb[((size_t)(TT - 4 + tt) * NN + m) * 64 + k], 0.f) : 0.f;
        sX[r][64 + k] = (m < NN) ? g_h2last[((size_t)tt * NN + m) * 64 + k] : 0.f;
    }
    for (int i = tid; i < 128 * 8; i += 256) sW[i >> 3][i & 7] = Wout[i];
    __syncthreads();
    int node = tid >> 3, o = tid & 7;
    float acc = bout[o];
    for (int k = 0; k < 128; k++) acc += sX[node][k] * sW[k][o];
    int m = n0 + node;
    if (m < NN) out[((size_t)tt * NN + m) * 8 + o] = acc;
}

// ---------------- launch ----------------------------------------------------------
extern "C" void kernel_launch(void* const* d_in, const int* in_sizes, int n_in,
                              void* d_out, int out_size) {
    const float* x      = (const float*)d_in[0];
    const int*   ei     = (const int*)d_in[1];
    const float* ew     = (const float*)d_in[2];
    const float* sWr    = (const float*)d_in[3];
    const float* sWroot = (const float*)d_in[4];
    const float* sb     = (const float*)d_in[5];
    const float* Wr1    = (const float*)d_in[6];
    const float* Wroot1 = (const float*)d_in[7];
    const float* b1     = (const float*)d_in[8];
    const float* Wr2    = (const float*)d_in[9];
    const float* Wroot2 = (const float*)d_in[10];
    const float* b2     = (const float*)d_in[11];
    const float* Wout   = (const float*)d_in[12];
    const float* bout   = (const float*)d_in[13];
    float* out = (float*)d_out;
    const int* src = ei;
    const int* dst = ei + EE;

    int nsm = 0;
    cudaDeviceGetAttribute(&nsm, cudaDevAttrMultiProcessorCount, 0);
    cudaFuncSetAttribute(k_chain, cudaFuncAttributeMaxDynamicSharedMemorySize,
                         CHAIN_SMEM);
    cudaFuncSetAttribute(k_pre, cudaFuncAttributeMaxDynamicSharedMemorySize,
                         PRE_SMEM);

    // CSR build
    k_zero_cursor<<<(NN + 255) / 256, 256>>>();
    k_deg<<<(EE + 255) / 256, 256>>>(dst);
    k_scan<<<1, 1024>>>();
    k_fill<<<(EE + 255) / 256, 256>>>(src, dst, ew);

    // SAGE embedding (exact fp32 -> emb; fp16 xr)
    dim3 aggGridT(2500, TT);
    k_aggx<<<aggGridT, 256>>>(x);
    k_sage<<<TT * NN / 64, 256>>>(x, sWr, sWroot, sb, out + EMB_OFF);

    // x-dependent gate halves (fp16 agg + fp16 mma + fp16 pre)
    k_aggh<<<aggGridT, 256>>>();
    k_pre<<<nsm, 512, PRE_SMEM>>>(Wr1, Wroot1, b1, Wr2, Wroot2, b2);

    // Fused persistent chain (ticket-based tile stealing)
    k_chain<<<nsm, 512, CHAIN_SMEM>>>(Wr1, Wroot1, Wr2, Wroot2, out + C2_OFF);

    k_out<<<dim3(NN / 32, 4), 256>>>(out + EMB_OFF, Wout, bout, out + OUT_OFF);
}

// round 13
// speedup vs baseline: 1.2526x; 1.0597x over previous
#include <cuda_runtime.h>
#include <cuda_fp16.h>
#include <math.h>

#define TT 12
#define NN 20000
#define EE 400000
#define FF 32
#define HH 64
#define OO 8

// Output layout (flattened tuple): out[4,N,8] | c2[N,64] | emb[T,N,64]
#define OUT_OFF 0
#define C2_OFF  (4*NN*OO)                 // 640000
#define EMB_OFF (C2_OFF + NN*HH)          // 1920000

#define CH_TILES ((NN + 31) / 32)         // 625 chain tiles (32 rows)
#define PRE_TILES (TT * NN / 128)         // 1875

// ---------------- scratch (static device globals; allocation-free at runtime) ----
__device__ int      g_rowptr[NN + 1];
__device__ int      g_cursor[NN];
__device__ int      g_csr_src[EE];
__device__ float    g_csr_w[EE];
__device__ unsigned g_xrh[TT * NN * 32];         // relu(emb) as half2 pairs
__device__ float    g_aggx[TT * NN * FF];        // wmean(x) per t (fp32, emb path)
__device__ unsigned g_aggxrh[TT * NN * 32];      // wmean(xr) as half2 pairs
// gate pre-contrib, GATE-INTERLEAVED: word index = m*128 + hcpair*4 + gate
__device__ unsigned g_preh[2][TT * NN * 128];
__device__ unsigned g_hh[2][NN * 32];            // fp16 hidden state (half2 words)
__device__ float    g_c[NN * HH];
__device__ float    g_h2last[4 * NN * HH];       // h2 for last 4 steps (fp32)
__device__ int      g_ctr[2 * TT];               // per-step tile tickets

// grid barrier state
__device__ unsigned g_bar_count = 0;
__device__ volatile unsigned g_bar_gen = 0;

// ---------------- helpers ----------------------------------------------------------
__device__ __forceinline__ void mma16(float* c, const uint4 a, const uint2 b) {
    asm volatile(
        "mma.sync.aligned.m16n8k16.row.col.f32.f16.f16.f32 "
        "{%0,%1,%2,%3},{%4,%5,%6,%7},{%8,%9},{%0,%1,%2,%3};"
        : "+f"(c[0]), "+f"(c[1]), "+f"(c[2]), "+f"(c[3])
        : "r"(a.x), "r"(a.y), "r"(a.z), "r"(a.w), "r"(b.x), "r"(b.y));
}
__device__ __forceinline__ unsigned h2u(float lo, float hi) {
    __half2 h = __floats2half2_rn(lo, hi);
    return *(unsigned*)&h;
}
__device__ __forceinline__ float2 u2f2(unsigned u) {
    return __half22float2(*(const __half2*)&u);
}
__device__ __forceinline__ unsigned long long pk2(float lo, float hi) {
    unsigned long long r;
    asm("mov.b64 %0, {%1,%2};" : "=l"(r) : "f"(lo), "f"(hi));
    return r;
}
__device__ __forceinline__ void upk2(unsigned long long v, float& lo, float& hi) {
    asm("mov.b64 {%0,%1}, %2;" : "=f"(lo), "=f"(hi) : "l"(v));
}
__device__ __forceinline__ unsigned long long ffma2(unsigned long long a,
                                                    unsigned long long b,
                                                    unsigned long long c) {
    unsigned long long d;
    asm("fma.rn.f32x2 %0, %1, %2, %3;" : "=l"(d) : "l"(a), "l"(b), "l"(c));
    return d;
}
__device__ __forceinline__ unsigned ld_acq(volatile unsigned* p) {
    unsigned v;
    asm volatile("ld.acquire.gpu.u32 %0, [%1];"
                 : "=r"(v) : "l"((const unsigned*)p) : "memory");
    return v;
}
__device__ __forceinline__ void gridbar(unsigned& gen) {
    __syncthreads();
    if (threadIdx.x == 0) {
        __threadfence();
        unsigned t = atomicAdd(&g_bar_count, 1);
        if (t == gridDim.x - 1) {
            g_bar_count = 0;
            __threadfence();
            asm volatile("st.release.gpu.u32 [%0], %1;"
                         :: "l"((unsigned*)&g_bar_gen), "r"(gen + 1) : "memory");
        } else {
            while (ld_acq(&g_bar_gen) != gen + 1) __nanosleep(16);
        }
    }
    gen++;
    __syncthreads();
}

// ---------------- CSR construction ------------------------------------------------
__global__ void k_zero_cursor() {
    int i = blockIdx.x * blockDim.x + threadIdx.x;
    if (i < NN) g_cursor[i] = 0;
}

__global__ void k_deg(const int* __restrict__ dst) {
    int e = blockIdx.x * blockDim.x + threadIdx.x;
    if (e < EE) atomicAdd(&g_cursor[dst[e]], 1);
}

__global__ void k_scan() {
    __shared__ int wsum[32];
    const int CH = 20;
    int tid = threadIdx.x;
    int base = tid * CH;
    int loc[CH];
    int s = 0;
#pragma unroll
    for (int i = 0; i < CH; i++) {
        int idx = base + i;
        int v = (idx < NN) ? g_cursor[idx] : 0;
        loc[i] = s;
        s += v;
    }
    int lane = tid & 31, w = tid >> 5;
    int inc = s;
#pragma unroll
    for (int o = 1; o < 32; o <<= 1) {
        int t = __shfl_up_sync(0xffffffffu, inc, o);
        if (lane >= o) inc += t;
    }
    if (lane == 31) wsum[w] = inc;
    __syncthreads();
    if (w == 0) {
        int v = wsum[lane];
#pragma unroll
        for (int o = 1; o < 32; o <<= 1) {
            int t = __shfl_up_sync(0xffffffffu, v, o);
            if (lane >= o) v += t;
        }
        wsum[lane] = v;
    }
    __syncthreads();
    int excl = inc - s + (w > 0 ? wsum[w - 1] : 0);
#pragma unroll
    for (int i = 0; i < CH; i++) {
        int idx = base + i;
        if (idx < NN) {
            int p = excl + loc[i];
            g_rowptr[idx] = p;
            g_cursor[idx] = p;
        }
    }
    if (tid == 0) g_rowptr[NN] = EE;
}

__global__ void k_fill(const int* __restrict__ src, const int* __restrict__ dst,
                       const float* __restrict__ ew) {
    int e = blockIdx.x * blockDim.x + threadIdx.x;
    if (e < EE) {
        int d = dst[e];
        int pos = atomicAdd(&g_cursor[d], 1);
        g_csr_src[pos] = src[e];
        g_csr_w[pos] = ew[e];
    }
}

// ---------------- wmean of x (fp32, emb path), MLP-4 edge loop, parallel T --------
__global__ void k_aggx(const float* __restrict__ xin) {
    int gw = (blockIdx.x * blockDim.x + threadIdx.x) >> 5;
    int lane = threadIdx.x & 31;
    if (gw >= NN) return;
    size_t toff = (size_t)blockIdx.y * NN * FF;
    const float* __restrict__ in = xin + toff;
    float* __restrict__ out = g_aggx + toff;

    int e0 = g_rowptr[gw], e1 = g_rowptr[gw + 1];
    float acc = 0.f;
    int e = e0;
    for (; e + 4 <= e1; e += 4) {
        int s0 = __ldg(&g_csr_src[e]);
        int s1 = __ldg(&g_csr_src[e + 1]);
        int s2 = __ldg(&g_csr_src[e + 2]);
        int s3 = __ldg(&g_csr_src[e + 3]);
        float w0 = __ldg(&g_csr_w[e]);
        float w1 = __ldg(&g_csr_w[e + 1]);
        float w2 = __ldg(&g_csr_w[e + 2]);
        float w3 = __ldg(&g_csr_w[e + 3]);
        float v0 = __ldg(&in[(size_t)s0 * FF + lane]);
        float v1 = __ldg(&in[(size_t)s1 * FF + lane]);
        float v2 = __ldg(&in[(size_t)s2 * FF + lane]);
        float v3 = __ldg(&in[(size_t)s3 * FF + lane]);
        acc += w0 * v0 + w1 * v1 + w2 * v2 + w3 * v3;
    }
    for (; e < e1; e++) {
        int s = __ldg(&g_csr_src[e]);
        float w = __ldg(&g_csr_w[e]);
        acc += w * __ldg(&in[(size_t)s * FF + lane]);
    }
    out[(size_t)gw * FF + lane] = acc / (float)max(e1 - e0, 1);
}

// ---------------- wmean of xr (fp16 in/out), MLP-4, parallel T --------------------
__global__ void k_aggh() {
    int gw = (blockIdx.x * blockDim.x + threadIdx.x) >> 5;
    int lane = threadIdx.x & 31;
    if (gw >= NN) return;
    size_t toff = (size_t)blockIdx.y * NN * 32;
    const unsigned* __restrict__ in = g_xrh + toff;
    unsigned* __restrict__ out = g_aggxrh + toff;

    int e0 = g_rowptr[gw], e1 = g_rowptr[gw + 1];
    float ax = 0.f, ay = 0.f;
    int e = e0;
    for (; e + 4 <= e1; e += 4) {
        int s0 = __ldg(&g_csr_src[e]);
        int s1 = __ldg(&g_csr_src[e + 1]);
        int s2 = __ldg(&g_csr_src[e + 2]);
        int s3 = __ldg(&g_csr_src[e + 3]);
        float w0 = __ldg(&g_csr_w[e]);
        float w1 = __ldg(&g_csr_w[e + 1]);
        float w2 = __ldg(&g_csr_w[e + 2]);
        float w3 = __ldg(&g_csr_w[e + 3]);
        float2 v0 = u2f2(__ldg(&in[(size_t)s0 * 32 + lane]));
        float2 v1 = u2f2(__ldg(&in[(size_t)s1 * 32 + lane]));
        float2 v2 = u2f2(__ldg(&in[(size_t)s2 * 32 + lane]));
        float2 v3 = u2f2(__ldg(&in[(size_t)s3 * 32 + lane]));
        ax += w0 * v0.x + w1 * v1.x + w2 * v2.x + w3 * v3.x;
        ay += w0 * v0.y + w1 * v1.y + w2 * v2.y + w3 * v3.y;
    }
    for (; e < e1; e++) {
        int s = __ldg(&g_csr_src[e]);
        float w = __ldg(&g_csr_w[e]);
        float2 v = u2f2(__ldg(&in[(size_t)s * 32 + lane]));
        ax += w * v.x;
        ay += w * v.y;
    }
    float inv = 1.f / (float)max(e1 - e0, 1);
    out[(size_t)gw * 32 + lane] = h2u(ax * inv, ay * inv);
}

// ---------------- SAGE (f32x2 core, exact fp32): emb fp32; xrh fp16 ---------------
__global__ __launch_bounds__(256, 2) void k_sage(const float* __restrict__ x,
                                                 const float* __restrict__ Wr,
                                                 const float* __restrict__ Wroot,
                                                 const float* __restrict__ b,
                                                 float* __restrict__ emb) {
    __shared__ float sA[64][33];
    __shared__ float sW[32][66];
    int m0 = blockIdx.x * 64;
    int tid = threadIdx.x;
    int tr = tid / 16, tc = tid % 16;
    unsigned long long acc[4][2];
#pragma unroll
    for (int i = 0; i < 4; i++)
#pragma unroll
        for (int j2 = 0; j2 < 2; j2++) acc[i][j2] = 0ull;
    for (int kb = 0; kb < 2; kb++) {
        const float* Asrc = kb ? x : g_aggx;
        const float* Wsrc = kb ? Wroot : Wr;
        __syncthreads();
        for (int i = tid; i < 64 * 32; i += 256) {
            int r = i >> 5, k = i & 31;
            sA[r][k] = Asrc[(size_t)(m0 + r) * 32 + k];
        }
        for (int i = tid; i < 32 * 64; i += 256) {
            int r = i >> 6, cc = i & 63;
            sW[r][cc] = Wsrc[(size_t)r * 64 + cc];
        }
        __syncthreads();
#pragma unroll
        for (int k = 0; k < 32; k++) {
            unsigned long long a2[4];
#pragma unroll
            for (int i = 0; i < 4; i++) {
                float av = sA[tr * 4 + i][k];
                a2[i] = pk2(av, av);
            }
#pragma unroll
            for (int j2 = 0; j2 < 2; j2++) {
                unsigned long long w2 = *(const unsigned long long*)&sW[k][tc * 4 + j2 * 2];
#pragma unroll
                for (int i = 0; i < 4; i++) acc[i][j2] = ffma2(a2[i], w2, acc[i][j2]);
            }
        }
    }
#pragma unroll
    for (int i = 0; i < 4; i++) {
        int m = m0 + tr * 4 + i;
        size_t mrow = (size_t)m * 64;
#pragma unroll
        for (int j2 = 0; j2 < 2; j2++) {
            float v0, v1;
            upk2(acc[i][j2], v0, v1);
            int c0 = tc * 4 + j2 * 2;
            v0 += b[c0];
            v1 += b[c0 + 1];
            emb[mrow + c0] = v0;
            emb[mrow + c0 + 1] = v1;
            g_xrh[(size_t)m * 32 + (c0 >> 1)] = h2u(fmaxf(v0, 0.f), fmaxf(v1, 0.f));
        }
    }
}

// ---------------- persistent PRE (fp16 mma): both layers, W staged once/SM --------
// Writes preh GATE-INTERLEAVED: uint4 per (m, hc-pair) holding {i,f,g,o}.
#define PRE_SMEM ((8 * 32 * 32 * 2 + 8 * 8 * 32 * 4) * 4)
__global__ __launch_bounds__(512, 1) void k_pre(const float* __restrict__ Wr1,
                                                const float* __restrict__ Wroot1,
                                                const float* __restrict__ b1,
                                                const float* __restrict__ Wr2,
                                                const float* __restrict__ Wroot2,
                                                const float* __restrict__ b2) {
    extern __shared__ unsigned smem[];
    unsigned* sW = smem;
    unsigned* sA = smem + 8 * 32 * 32 * 2;
    int tid = threadIdx.x;
    int warp = tid >> 5, lane = tid & 31;
    int wm = warp >> 2, wn = warp & 3;
    int gid = lane >> 2, tig = lane & 3;

    for (int L = 0; L < 2; L++) {
        const float* __restrict__ Wr = L ? Wr2 : Wr1;
        const float* __restrict__ Wroot = L ? Wroot2 : Wroot1;
        const float* __restrict__ bias = L ? b2 : b1;
        unsigned* __restrict__ preh = g_preh[L];
        __syncthreads();
        for (int i = tid; i < 64 * 256; i += 512) {
            int k2 = i >> 8, n = i & 255;
            int k = k2 * 2;
            float v0, v1;
            if (k < 64) {
                v0 = Wr[(size_t)k * 256 + n];
                v1 = Wr[(size_t)(k + 1) * 256 + n];
            } else {
                v0 = Wroot[(size_t)(k - 64) * 256 + n];
                v1 = Wroot[(size_t)(k - 63) * 256 + n];
            }
            int kc = k2 >> 3, breg = (k2 >> 2) & 1;
            int bl = (n & 7) * 4 + (k2 & 3);
            sW[((kc * 32 + (n >> 3)) * 32 + bl) * 2 + breg] = h2u(v0, v1);
        }
        __syncthreads();

        for (int tile = blockIdx.x; tile < PRE_TILES; tile += gridDim.x) {
            int m0 = tile * 128;
            __syncthreads();
            for (int i = tid; i < 128 * 64; i += 512) {
                int r = i >> 6, c2 = i & 63;
                size_t m32 = (size_t)(m0 + r) * 32;
                unsigned u = (c2 < 32) ? g_aggxrh[m32 + c2] : g_xrh[m32 + (c2 - 32)];
                int mf = r >> 4, kc = c2 >> 3;
                int reg = ((c2 >> 2) & 1) * 2 + ((r >> 3) & 1);
                int al = (r & 7) * 4 + (c2 & 3);
                sA[((mf * 8 + kc) * 32 + al) * 4 + reg] = u;
            }
            __syncthreads();
            float acc[2][4][2][4];
#pragma unroll
            for (int mf = 0; mf < 2; mf++)
#pragma unroll
                for (int g = 0; g < 4; g++)
#pragma unroll
                    for (int hh = 0; hh < 2; hh++)
#pragma unroll
                        for (int q = 0; q < 4; q++) acc[mf][g][hh][q] = 0.f;
#pragma unroll
            for (int kc = 0; kc < 8; kc++) {
                uint4 a[2];
#pragma unroll
                for (int mf = 0; mf < 2; mf++)
                    a[mf] = ((const uint4*)sA)[((wm * 2 + mf) * 8 + kc) * 32 + lane];
#pragma unroll
                for (int g = 0; g < 4; g++)
#pragma unroll
                    for (int hh = 0; hh < 2; hh++) {
                        int n8 = g * 8 + wn * 2 + hh;
                        uint2 b = ((const uint2*)sW)[(kc * 32 + n8) * 32 + lane];
#pragma unroll
                        for (int mf = 0; mf < 2; mf++)
                            mma16(acc[mf][g][hh], a[mf], b);
                    }
            }
            // epilogue: gate-interleaved uint4 stores
#pragma unroll
            for (int mf = 0; mf < 2; mf++)
#pragma unroll
                for (int rr = 0; rr < 2; rr++) {
                    int m = m0 + wm * 32 + mf * 16 + gid + rr * 8;
#pragma unroll
                    for (int hh = 0; hh < 2; hh++) {
                        int hcL = wn * 16 + hh * 8 + tig * 2;   // column pair base
                        uint4 u;
                        u.x = h2u(acc[mf][0][hh][rr * 2 + 0] + bias[hcL],
                                  acc[mf][0][hh][rr * 2 + 1] + bias[hcL + 1]);
                        u.y = h2u(acc[mf][1][hh][rr * 2 + 0] + bias[64 + hcL],
                                  acc[mf][1][hh][rr * 2 + 1] + bias[64 + hcL + 1]);
                        u.z = h2u(acc[mf][2][hh][rr * 2 + 0] + bias[128 + hcL],
                                  acc[mf][2][hh][rr * 2 + 1] + bias[128 + hcL + 1]);
                        u.w = h2u(acc[mf][3][hh][rr * 2 + 0] + bias[192 + hcL],
                                  acc[mf][3][hh][rr * 2 + 1] + bias[192 + hcL + 1]);
                        ((uint4*)preh)[(size_t)m * 32 + (wn * 8 + hh * 4 + tig)] = u;
                    }
                }
        }
    }
}

// ---------------- persistent fused LSTM chain: 32-row tiles, tickets --------------
#define CHAIN_SMEM (160 * 1024)
__global__ __launch_bounds__(512, 1) void k_chain(const float* __restrict__ Wr1,
                                                  const float* __restrict__ Wroot1,
                                                  const float* __restrict__ Wr2,
                                                  const float* __restrict__ Wroot2,
                                                  float* __restrict__ outC2) {
    extern __shared__ unsigned smem[];
    unsigned* sW = smem;                      // 16384 u32
    unsigned* sA = smem + 8 * 32 * 32 * 2;    // 2048 u32 (32-row tile)
    __shared__ int sTicket;
    int tid = threadIdx.x;
    int warp = tid >> 5, lane = tid & 31;
    int wm = warp >> 3, wn = warp & 7;        // 2 x 8 warps over 32x256 tile
    int gid = lane >> 2, tig = lane & 3;
    unsigned gen = g_bar_gen;

    // init h0, c0, per-step tickets
    for (int i = blockIdx.x * 512 + tid; i < NN * 32; i += gridDim.x * 512)
        g_hh[0][i] = 0u;
    for (int i = blockIdx.x * 512 + tid; i < NN * HH; i += gridDim.x * 512)
        g_c[i] = 0.f;
    if (blockIdx.x == 0 && tid < 2 * TT) g_ctr[tid] = 0;
    gridbar(gen);

    int par = 0;
    for (int L = 0; L < 2; L++) {
        const float* __restrict__ Wr = L ? Wr2 : Wr1;
        const float* __restrict__ Wroot = L ? Wroot2 : Wroot1;
        for (int i = tid; i < 64 * 256; i += 512) {
            int k2 = i >> 8, n = i & 255;
            int k = k2 * 2;
            float v0, v1;
            if (k < 64) {
                v0 = Wr[(size_t)(64 + k) * 256 + n];
                v1 = Wr[(size_t)(65 + k) * 256 + n];
            } else {
                v0 = Wroot[(size_t)k * 256 + n];
                v1 = Wroot[(size_t)(k + 1) * 256 + n];
            }
            int kc = k2 >> 3, breg = (k2 >> 2) & 1;
            int bl = (n & 7) * 4 + (k2 & 3);
            sW[((kc * 32 + (n >> 3)) * 32 + bl) * 2 + breg] = h2u(v0, v1);
        }
        __syncthreads();
        const unsigned* __restrict__ preL = g_preh[L];

        for (int t = 0; t < TT; t++) {
            const unsigned* __restrict__ hin = g_hh[par];
            unsigned* __restrict__ hout = g_hh[par ^ 1];
            const uint4* __restrict__ pre4 =
                (const uint4*)(preL + (size_t)t * NN * 128);
            int store = (L == 1 && t >= TT - 4) ? (t - (TT - 4)) : -1;
            int step_id = L * TT + t;

            for (;;) {
                __syncthreads();   // previous tile fully consumed before re-staging
                if (tid == 0) sTicket = atomicAdd(&g_ctr[step_id], 1);
                __syncthreads();
                int tile = sTicket;
                if (tile >= CH_TILES) break;
                int m0 = tile * 32;

                // gather: 16 warps x 2 rows; lane = feature pair (MLP-4 + tail)
#pragma unroll
                for (int rq = 0; rq < 2; rq++) {
                    int r = warp * 2 + rq;
                    int m = m0 + r;
                    unsigned aggu = 0u, hu = 0u;
                    if (m < NN) {
                        int e0 = g_rowptr[m], e1 = g_rowptr[m + 1];
                        float ax = 0.f, ay = 0.f;
                        int e = e0;
                        for (; e + 4 <= e1; e += 4) {
                            int s0 = __ldg(&g_csr_src[e]);
                            int s1 = __ldg(&g_csr_src[e + 1]);
                            int s2 = __ldg(&g_csr_src[e + 2]);
                            int s3 = __ldg(&g_csr_src[e + 3]);
                            float w0 = __ldg(&g_csr_w[e]);
                            float w1 = __ldg(&g_csr_w[e + 1]);
                            float w2 = __ldg(&g_csr_w[e + 2]);
                            float w3 = __ldg(&g_csr_w[e + 3]);
                            float2 v0 = u2f2(__ldg(&hin[(size_t)s0 * 32 + lane]));
                            float2 v1 = u2f2(__ldg(&hin[(size_t)s1 * 32 + lane]));
                            float2 v2 = u2f2(__ldg(&hin[(size_t)s2 * 32 + lane]));
                            float2 v3 = u2f2(__ldg(&hin[(size_t)s3 * 32 + lane]));
                            ax += w0 * v0.x + w1 * v1.x + w2 * v2.x + w3 * v3.x;
                            ay += w0 * v0.y + w1 * v1.y + w2 * v2.y + w3 * v3.y;
                        }
                        for (; e < e1; e++) {
                            int s = __ldg(&g_csr_src[e]);
                            float w = __ldg(&g_csr_w[e]);
                            float2 v = u2f2(__ldg(&hin[(size_t)s * 32 + lane]));
                            ax += w * v.x;
                            ay += w * v.y;
                        }
                        float inv = 1.f / (float)max(e1 - e0, 1);
                        aggu = h2u(ax * inv, ay * inv);
                        hu = hin[(size_t)m * 32 + lane];
                    }
                    int mf = r >> 4;
                    int al = (r & 7) * 4 + (lane & 3);
                    int regc = ((lane >> 2) & 1) * 2 + ((r >> 3) & 1);
                    int kcA = lane >> 3;
                    sA[((mf * 8 + kcA) * 32 + al) * 4 + regc] = aggu;
                    sA[((mf * 8 + 4 + kcA) * 32 + al) * 4 + regc] = hu;
                }
                __syncthreads();
                float acc[4][4];
#pragma unroll
                for (int g = 0; g < 4; g++)
#pragma unroll
                    for (int q = 0; q < 4; q++) acc[g][q] = 0.f;
#pragma unroll
                for (int kc = 0; kc < 8; kc++) {
                    uint4 a = ((const uint4*)sA)[(wm * 8 + kc) * 32 + lane];
#pragma unroll
                    for (int g = 0; g < 4; g++) {
                        int n8 = g * 8 + wn;
                        uint2 b = ((const uint2*)sW)[(kc * 32 + n8) * 32 + lane];
                        mma16(acc[g], a, b);
                    }
                }
#pragma unroll
                for (int rr = 0; rr < 2; rr++) {
                    int m = m0 + wm * 16 + gid + rr * 8;
                    if (m >= NN) continue;
                    int hc = wn * 8 + tig * 2;
                    // single uint4 read: all 4 gates for this column pair
                    uint4 p4 = __ldg(&pre4[(size_t)m * 32 + (wn * 4 + tig)]);
                    float2 pi = u2f2(p4.x);
                    float2 pf = u2f2(p4.y);
                    float2 pg = u2f2(p4.z);
                    float2 po = u2f2(p4.w);
                    size_t hb = (size_t)m * 64 + hc;
                    float2 cold = *(const float2*)&g_c[hb];
                    float gi0 = acc[0][rr * 2 + 0] + pi.x;
                    float gi1 = acc[0][rr * 2 + 1] + pi.y;
                    float gf0 = acc[1][rr * 2 + 0] + pf.x;
                    float gf1 = acc[1][rr * 2 + 1] + pf.y;
                    float gg0 = acc[2][rr * 2 + 0] + pg.x;
                    float gg1 = acc[2][rr * 2 + 1] + pg.y;
                    float go0 = acc[3][rr * 2 + 0] + po.x;
                    float go1 = acc[3][rr * 2 + 1] + po.y;
                    float si0 = __fdividef(1.f, 1.f + __expf(-gi0));
                    float si1 = __fdividef(1.f, 1.f + __expf(-gi1));
                    float sf0 = __fdividef(1.f, 1.f + __expf(-gf0));
                    float sf1 = __fdividef(1.f, 1.f + __expf(-gf1));
                    float so0 = __fdividef(1.f, 1.f + __expf(-go0));
                    float so1 = __fdividef(1.f, 1.f + __expf(-go1));
                    float2 cn, hn;
                    cn.x = sf0 * cold.x + si0 * tanhf(gg0);
                    cn.y = sf1 * cold.y + si1 * tanhf(gg1);
                    hn.x = so0 * tanhf(cn.x);
                    hn.y = so1 * tanhf(cn.y);
                    *(float2*)&g_c[hb] = cn;
                    hout[(size_t)m * 32 + (hc >> 1)] = h2u(hn.x, hn.y);
                    if (store >= 0)
                        *(float2*)&g_h2last[(size_t)store * NN * 64 + hb] = hn;
                }
            }
            gridbar(gen);
            par ^= 1;
        }
        __syncthreads();
    }

    for (int i = blockIdx.x * 512 + tid; i < NN * HH; i += gridDim.x * 512)
        outC2[i] = g_c[i];
}

// ---------------- final projection: out = [relu(emb), h2][-4:] @ W_out + b_out ----
__global__ __launch_bounds__(256) void k_out(const float* __restrict__ emb,
                                             const float* __restrict__ Wout,
                                             const float* __restrict__ bout,
                                             float* __restrict__ out) {
    __shared__ float sX[32][129];
    __shared__ float sW[128][9];
    int tt = blockIdx.y;
    int n0 = blockIdx.x * 32;
    int tid = threadIdx.x;
    for (int i = tid; i < 32 * 64; i += 256) {
        int r = i >> 6, k = i & 63;
        int m = n0 + r;
        sX[r][k] = (m < NN)
            ? fmaxf(emb[((size_t)(TT - 4 + tt) * NN + m) * 64 + k], 0.f) : 0.f;
        sX[r][64 + k] = (m < NN) ? g_h2last[((size_t)tt * NN + m) * 64 + k] : 0.f;
    }
    for (int i = tid; i < 128 * 8; i += 256) sW[i >> 3][i & 7] = Wout[i];
    __syncthreads();
    int node = tid >> 3, o = tid & 7;
    float acc = bout[o];
    for (int k = 0; k < 128; k++) acc += sX[node][k] * sW[k][o];
    int m = n0 + node;
    if (m < NN) out[((size_t)tt * NN + m) * 8 + o] = acc;
}

// ---------------- launch ----------------------------------------------------------
extern "C" void kernel_launch(void* const* d_in, const int* in_sizes, int n_in,
                              void* d_out, int out_size) {
    const float* x      = (const float*)d_in[0];
    const int*   ei     = (const int*)d_in[1];
    const float* ew     = (const float*)d_in[2];
    const float* sWr    = (const float*)d_in[3];
    const float* sWroot = (const float*)d_in[4];
    const float* sb     = (const float*)d_in[5];
    const float* Wr1    = (const float*)d_in[6];
    const float* Wroot1 = (const float*)d_in[7];
    const float* b1     = (const float*)d_in[8];
    const float* Wr2    = (const float*)d_in[9];
    const float* Wroot2 = (const float*)d_in[10];
    const float* b2     = (const float*)d_in[11];
    const float* Wout   = (const float*)d_in[12];
    const float* bout   = (const float*)d_in[13];
    float* out = (float*)d_out;
    const int* src = ei;
    const int* dst = ei + EE;

    int nsm = 0;
    cudaDeviceGetAttribute(&nsm, cudaDevAttrMultiProcessorCount, 0);
    cudaFuncSetAttribute(k_chain, cudaFuncAttributeMaxDynamicSharedMemorySize,
                         CHAIN_SMEM);
    cudaFuncSetAttribute(k_pre, cudaFuncAttributeMaxDynamicSharedMemorySize,
                         PRE_SMEM);

    // CSR build
    k_zero_cursor<<<(NN + 255) / 256, 256>>>();
    k_deg<<<(EE + 255) / 256, 256>>>(dst);
    k_scan<<<1, 1024>>>();
    k_fill<<<(EE + 255) / 256, 256>>>(src, dst, ew);

    // SAGE embedding (exact fp32 -> emb; fp16 xr)
    dim3 aggGridT(2500, TT);
    k_aggx<<<aggGridT, 256>>>(x);
    k_sage<<<TT * NN / 64, 256>>>(x, sWr, sWroot, sb, out + EMB_OFF);

    // x-dependent gate halves (fp16 agg + fp16 mma + gate-interleaved fp16 pre)
    k_aggh<<<aggGridT, 256>>>();
    k_pre<<<nsm, 512, PRE_SMEM>>>(Wr1, Wroot1, b1, Wr2, Wroot2, b2);

    // Fused persistent chain (ticket-based tile stealing, uint4 pre reads)
    k_chain<<<nsm, 512, CHAIN_SMEM>>>(Wr1, Wroot1, Wr2, Wroot2, out + C2_OFF);

    k_out<<<dim3(NN / 32, 4), 256>>>(out + EMB_OFF, Wout, bout, out + OUT_OFF);
}

// round 16
// speedup vs baseline: 1.2536x; 1.0008x over previous
#include <cuda_runtime.h>
#include <cuda_fp16.h>
#include <math.h>

#define TT 12
#define NN 20000
#define EE 400000
#define FF 32
#define HH 64
#define OO 8

// Output layout (flattened tuple): out[4,N,8] | c2[N,64] | emb[T,N,64]
#define OUT_OFF 0
#define C2_OFF  (4*NN*OO)                 // 640000
#define EMB_OFF (C2_OFF + NN*HH)          // 1920000

#define CH_TILES ((NN + 31) / 32)         // 625 chain tiles (32 rows)
#define PRE_TILES (TT * NN / 128)         // 1875

// ---------------- scratch (static device globals; allocation-free at runtime) ----
__device__ int      g_rowptr[NN + 1];
__device__ int      g_cursor[NN];
__device__ int      g_csr_src[EE];
__device__ float    g_csr_w[EE];
__device__ unsigned g_xrh[TT * NN * 32];         // relu(emb) as half2 pairs
__device__ float    g_aggx[TT * NN * FF];        // wmean(x) per t (fp32, emb path)
__device__ unsigned g_aggxrh[TT * NN * 32];      // wmean(xr) as half2 pairs
// gate pre-contrib, GATE-INTERLEAVED: word index = m*128 + hcpair*4 + gate
__device__ unsigned g_preh[2][TT * NN * 128];
__device__ unsigned g_hh[2][NN * 32];            // fp16 hidden state (half2 words)
__device__ float    g_c[NN * HH];
__device__ float    g_h2last[4 * NN * HH];       // h2 for last 4 steps (fp32)
__device__ int      g_ctr[2 * TT];               // per-step tile tickets

// grid barrier state
__device__ unsigned g_bar_count = 0;
__device__ volatile unsigned g_bar_gen = 0;

// ---------------- helpers ----------------------------------------------------------
__device__ __forceinline__ void mma16(float* c, const uint4 a, const uint2 b) {
    asm volatile(
        "mma.sync.aligned.m16n8k16.row.col.f32.f16.f16.f32 "
        "{%0,%1,%2,%3},{%4,%5,%6,%7},{%8,%9},{%0,%1,%2,%3};"
        : "+f"(c[0]), "+f"(c[1]), "+f"(c[2]), "+f"(c[3])
        : "r"(a.x), "r"(a.y), "r"(a.z), "r"(a.w), "r"(b.x), "r"(b.y));
}
__device__ __forceinline__ unsigned h2u(float lo, float hi) {
    __half2 h = __floats2half2_rn(lo, hi);
    return *(unsigned*)&h;
}
__device__ __forceinline__ float2 u2f2(unsigned u) {
    return __half22float2(*(const __half2*)&u);
}
__device__ __forceinline__ unsigned long long pk2(float lo, float hi) {
    unsigned long long r;
    asm("mov.b64 %0, {%1,%2};" : "=l"(r) : "f"(lo), "f"(hi));
    return r;
}
__device__ __forceinline__ void upk2(unsigned long long v, float& lo, float& hi) {
    asm("mov.b64 {%0,%1}, %2;" : "=f"(lo), "=f"(hi) : "l"(v));
}
__device__ __forceinline__ unsigned long long ffma2(unsigned long long a,
                                                    unsigned long long b,
                                                    unsigned long long c) {
    unsigned long long d;
    asm("fma.rn.f32x2 %0, %1, %2, %3;" : "=l"(d) : "l"(a), "l"(b), "l"(c));
    return d;
}
__device__ __forceinline__ unsigned ld_acq(volatile unsigned* p) {
    unsigned v;
    asm volatile("ld.acquire.gpu.u32 %0, [%1];"
                 : "=r"(v) : "l"((const unsigned*)p) : "memory");
    return v;
}
__device__ __forceinline__ void gridbar(unsigned& gen) {
    __syncthreads();
    if (threadIdx.x == 0) {
        __threadfence();
        unsigned t = atomicAdd(&g_bar_count, 1);
        if (t == gridDim.x - 1) {
            g_bar_count = 0;
            __threadfence();
            asm volatile("st.release.gpu.u32 [%0], %1;"
                         :: "l"((unsigned*)&g_bar_gen), "r"(gen + 1) : "memory");
        } else {
            while (ld_acq(&g_bar_gen) != gen + 1) __nanosleep(16);
        }
    }
    gen++;
    __syncthreads();
}

// ---------------- CSR construction ------------------------------------------------
__global__ void k_zero_cursor() {
    int i = blockIdx.x * blockDim.x + threadIdx.x;
    if (i < NN) g_cursor[i] = 0;
}

__global__ void k_deg(const int* __restrict__ dst) {
    int e = blockIdx.x * blockDim.x + threadIdx.x;
    if (e < EE) atomicAdd(&g_cursor[dst[e]], 1);
}

__global__ void k_scan() {
    __shared__ int wsum[32];
    const int CH = 20;
    int tid = threadIdx.x;
    int base = tid * CH;
    int loc[CH];
    int s = 0;
#pragma unroll
    for (int i = 0; i < CH; i++) {
        int idx = base + i;
        int v = (idx < NN) ? g_cursor[idx] : 0;
        loc[i] = s;
        s += v;
    }
    int lane = tid & 31, w = tid >> 5;
    int inc = s;
#pragma unroll
    for (int o = 1; o < 32; o <<= 1) {
        int t = __shfl_up_sync(0xffffffffu, inc, o);
        if (lane >= o) inc += t;
    }
    if (lane == 31) wsum[w] = inc;
    __syncthreads();
    if (w == 0) {
        int v = wsum[lane];
#pragma unroll
        for (int o = 1; o < 32; o <<= 1) {
            int t = __shfl_up_sync(0xffffffffu, v, o);
            if (lane >= o) v += t;
        }
        wsum[lane] = v;
    }
    __syncthreads();
    int excl = inc - s + (w > 0 ? wsum[w - 1] : 0);
#pragma unroll
    for (int i = 0; i < CH; i++) {
        int idx = base + i;
        if (idx < NN) {
            int p = excl + loc[i];
            g_rowptr[idx] = p;
            g_cursor[idx] = p;
        }
    }
    if (tid == 0) g_rowptr[NN] = EE;
}

__global__ void k_fill(const int* __restrict__ src, const int* __restrict__ dst,
                       const float* __restrict__ ew) {
    int e = blockIdx.x * blockDim.x + threadIdx.x;
    if (e < EE) {
        int d = dst[e];
        int pos = atomicAdd(&g_cursor[d], 1);
        g_csr_src[pos] = src[e];
        g_csr_w[pos] = ew[e];
    }
}

// ---------------- wmean of x (fp32, emb path), MLP-4 edge loop, parallel T --------
__global__ void k_aggx(const float* __restrict__ xin) {
    int gw = (blockIdx.x * blockDim.x + threadIdx.x) >> 5;
    int lane = threadIdx.x & 31;
    if (gw >= NN) return;
    size_t toff = (size_t)blockIdx.y * NN * FF;
    const float* __restrict__ in = xin + toff;
    float* __restrict__ out = g_aggx + toff;

    int e0 = g_rowptr[gw], e1 = g_rowptr[gw + 1];
    float acc = 0.f;
    int e = e0;
    for (; e + 4 <= e1; e += 4) {
        int s0 = __ldg(&g_csr_src[e]);
        int s1 = __ldg(&g_csr_src[e + 1]);
        int s2 = __ldg(&g_csr_src[e + 2]);
        int s3 = __ldg(&g_csr_src[e + 3]);
        float w0 = __ldg(&g_csr_w[e]);
        float w1 = __ldg(&g_csr_w[e + 1]);
        float w2 = __ldg(&g_csr_w[e + 2]);
        float w3 = __ldg(&g_csr_w[e + 3]);
        float v0 = __ldg(&in[(size_t)s0 * FF + lane]);
        float v1 = __ldg(&in[(size_t)s1 * FF + lane]);
        float v2 = __ldg(&in[(size_t)s2 * FF + lane]);
        float v3 = __ldg(&in[(size_t)s3 * FF + lane]);
        acc += w0 * v0 + w1 * v1 + w2 * v2 + w3 * v3;
    }
    for (; e < e1; e++) {
        int s = __ldg(&g_csr_src[e]);
        float w = __ldg(&g_csr_w[e]);
        acc += w * __ldg(&in[(size_t)s * FF + lane]);
    }
    out[(size_t)gw * FF + lane] = acc / (float)max(e1 - e0, 1);
}

// ---------------- wmean of xr (fp16 in/out), MLP-4, parallel T --------------------
__global__ void k_aggh() {
    int gw = (blockIdx.x * blockDim.x + threadIdx.x) >> 5;
    int lane = threadIdx.x & 31;
    if (gw >= NN) return;
    size_t toff = (size_t)blockIdx.y * NN * 32;
    const unsigned* __restrict__ in = g_xrh + toff;
    unsigned* __restrict__ out = g_aggxrh + toff;

    int e0 = g_rowptr[gw], e1 = g_rowptr[gw + 1];
    float ax = 0.f, ay = 0.f;
    int e = e0;
    for (; e + 4 <= e1; e += 4) {
        int s0 = __ldg(&g_csr_src[e]);
        int s1 = __ldg(&g_csr_src[e + 1]);
        int s2 = __ldg(&g_csr_src[e + 2]);
        int s3 = __ldg(&g_csr_src[e + 3]);
        float w0 = __ldg(&g_csr_w[e]);
        float w1 = __ldg(&g_csr_w[e + 1]);
        float w2 = __ldg(&g_csr_w[e + 2]);
        float w3 = __ldg(&g_csr_w[e + 3]);
        float2 v0 = u2f2(__ldg(&in[(size_t)s0 * 32 + lane]));
        float2 v1 = u2f2(__ldg(&in[(size_t)s1 * 32 + lane]));
        float2 v2 = u2f2(__ldg(&in[(size_t)s2 * 32 + lane]));
        float2 v3 = u2f2(__ldg(&in[(size_t)s3 * 32 + lane]));
        ax += w0 * v0.x + w1 * v1.x + w2 * v2.x + w3 * v3.x;
        ay += w0 * v0.y + w1 * v1.y + w2 * v2.y + w3 * v3.y;
    }
    for (; e < e1; e++) {
        int s = __ldg(&g_csr_src[e]);
        float w = __ldg(&g_csr_w[e]);
        float2 v = u2f2(__ldg(&in[(size_t)s * 32 + lane]));
        ax += w * v.x;
        ay += w * v.y;
    }
    float inv = 1.f / (float)max(e1 - e0, 1);
    out[(size_t)gw * 32 + lane] = h2u(ax * inv, ay * inv);
}

// ---------------- SAGE (f32x2 core, exact fp32): emb fp32; xrh fp16 ---------------
__global__ __launch_bounds__(256, 2) void k_sage(const float* __restrict__ x,
                                                 const float* __restrict__ Wr,
                                                 const float* __restrict__ Wroot,
                                                 const float* __restrict__ b,
                                                 float* __restrict__ emb) {
    __shared__ float sA[64][33];
    __shared__ float sW[32][66];
    int m0 = blockIdx.x * 64;
    int tid = threadIdx.x;
    int tr = tid / 16, tc = tid % 16;
    unsigned long long acc[4][2];
#pragma unroll
    for (int i = 0; i < 4; i++)
#pragma unroll
        for (int j2 = 0; j2 < 2; j2++) acc[i][j2] = 0ull;
    for (int kb = 0; kb < 2; kb++) {
        const float* Asrc = kb ? x : g_aggx;
        const float* Wsrc = kb ? Wroot : Wr;
        __syncthreads();
        for (int i = tid; i < 64 * 32; i += 256) {
            int r = i >> 5, k = i & 31;
            sA[r][k] = Asrc[(size_t)(m0 + r) * 32 + k];
        }
        for (int i = tid; i < 32 * 64; i += 256) {
            int r = i >> 6, cc = i & 63;
            sW[r][cc] = Wsrc[(size_t)r * 64 + cc];
        }
        __syncthreads();
#pragma unroll
        for (int k = 0; k < 32; k++) {
            unsigned long long a2[4];
#pragma unroll
            for (int i = 0; i < 4; i++) {
                float av = sA[tr * 4 + i][k];
                a2[i] = pk2(av, av);
            }
#pragma unroll
            for (int j2 = 0; j2 < 2; j2++) {
                unsigned long long w2 = *(const unsigned long long*)&sW[k][tc * 4 + j2 * 2];
#pragma unroll
                for (int i = 0; i < 4; i++) acc[i][j2] = ffma2(a2[i], w2, acc[i][j2]);
            }
        }
    }
#pragma unroll
    for (int i = 0; i < 4; i++) {
        int m = m0 + tr * 4 + i;
        size_t mrow = (size_t)m * 64;
#pragma unroll
        for (int j2 = 0; j2 < 2; j2++) {
            float v0, v1;
            upk2(acc[i][j2], v0, v1);
            int c0 = tc * 4 + j2 * 2;
            v0 += b[c0];
            v1 += b[c0 + 1];
            emb[mrow + c0] = v0;
            emb[mrow + c0 + 1] = v1;
            g_xrh[(size_t)m * 32 + (c0 >> 1)] = h2u(fmaxf(v0, 0.f), fmaxf(v1, 0.f));
        }
    }
}

// ---------------- persistent PRE (fp16 mma): both layers, W staged once/SM --------
// Writes preh GATE-INTERLEAVED: uint4 per (m, hc-pair) holding {i,f,g,o}.
#define PRE_SMEM ((8 * 32 * 32 * 2 + 8 * 8 * 32 * 4) * 4)
__global__ __launch_bounds__(512, 1) void k_pre(const float* __restrict__ Wr1,
                                                const float* __restrict__ Wroot1,
                                                const float* __restrict__ b1,
                                                const float* __restrict__ Wr2,
                                                const float* __restrict__ Wroot2,
                                                const float* __restrict__ b2) {
    extern __shared__ unsigned smem[];
    unsigned* sW = smem;
    unsigned* sA = smem + 8 * 32 * 32 * 2;
    int tid = threadIdx.x;
    int warp = tid >> 5, lane = tid & 31;
    int wm = warp >> 2, wn = warp & 3;
    int gid = lane >> 2, tig = lane & 3;

    for (int L = 0; L < 2; L++) {
        const float* __restrict__ Wr = L ? Wr2 : Wr1;
        const float* __restrict__ Wroot = L ? Wroot2 : Wroot1;
        const float* __restrict__ bias = L ? b2 : b1;
        unsigned* __restrict__ preh = g_preh[L];
        __syncthreads();
        for (int i = tid; i < 64 * 256; i += 512) {
            int k2 = i >> 8, n = i & 255;
            int k = k2 * 2;
            float v0, v1;
            if (k < 64) {
                v0 = Wr[(size_t)k * 256 + n];
                v1 = Wr[(size_t)(k + 1) * 256 + n];
            } else {
                v0 = Wroot[(size_t)(k - 64) * 256 + n];
                v1 = Wroot[(size_t)(k - 63) * 256 + n];
            }
            int kc = k2 >> 3, breg = (k2 >> 2) & 1;
            int bl = (n & 7) * 4 + (k2 & 3);
            sW[((kc * 32 + (n >> 3)) * 32 + bl) * 2 + breg] = h2u(v0, v1);
        }
        __syncthreads();

        for (int tile = blockIdx.x; tile < PRE_TILES; tile += gridDim.x) {
            int m0 = tile * 128;
            __syncthreads();
            for (int i = tid; i < 128 * 64; i += 512) {
                int r = i >> 6, c2 = i & 63;
                size_t m32 = (size_t)(m0 + r) * 32;
                unsigned u = (c2 < 32) ? g_aggxrh[m32 + c2] : g_xrh[m32 + (c2 - 32)];
                int mf = r >> 4, kc = c2 >> 3;
                int reg = ((c2 >> 2) & 1) * 2 + ((r >> 3) & 1);
                int al = (r & 7) * 4 + (c2 & 3);
                sA[((mf * 8 + kc) * 32 + al) * 4 + reg] = u;
            }
            __syncthreads();
            float acc[2][4][2][4];
#pragma unroll
            for (int mf = 0; mf < 2; mf++)
#pragma unroll
                for (int g = 0; g < 4; g++)
#pragma unroll
                    for (int hh = 0; hh < 2; hh++)
#pragma unroll
                        for (int q = 0; q < 4; q++) acc[mf][g][hh][q] = 0.f;
#pragma unroll
            for (int kc = 0; kc < 8; kc++) {
                uint4 a[2];
#pragma unroll
                for (int mf = 0; mf < 2; mf++)
                    a[mf] = ((const uint4*)sA)[((wm * 2 + mf) * 8 + kc) * 32 + lane];
#pragma unroll
                for (int g = 0; g < 4; g++)
#pragma unroll
                    for (int hh = 0; hh < 2; hh++) {
                        int n8 = g * 8 + wn * 2 + hh;
                        uint2 b = ((const uint2*)sW)[(kc * 32 + n8) * 32 + lane];
#pragma unroll
                        for (int mf = 0; mf < 2; mf++)
                            mma16(acc[mf][g][hh], a[mf], b);
                    }
            }
            // epilogue: gate-interleaved uint4 stores
#pragma unroll
            for (int mf = 0; mf < 2; mf++)
#pragma unroll
                for (int rr = 0; rr < 2; rr++) {
                    int m = m0 + wm * 32 + mf * 16 + gid + rr * 8;
#pragma unroll
                    for (int hh = 0; hh < 2; hh++) {
                        int hcL = wn * 16 + hh * 8 + tig * 2;   // column pair base
                        uint4 u;
                        u.x = h2u(acc[mf][0][hh][rr * 2 + 0] + bias[hcL],
                                  acc[mf][0][hh][rr * 2 + 1] + bias[hcL + 1]);
                        u.y = h2u(acc[mf][1][hh][rr * 2 + 0] + bias[64 + hcL],
                                  acc[mf][1][hh][rr * 2 + 1] + bias[64 + hcL + 1]);
                        u.z = h2u(acc[mf][2][hh][rr * 2 + 0] + bias[128 + hcL],
                                  acc[mf][2][hh][rr * 2 + 1] + bias[128 + hcL + 1]);
                        u.w = h2u(acc[mf][3][hh][rr * 2 + 0] + bias[192 + hcL],
                                  acc[mf][3][hh][rr * 2 + 1] + bias[192 + hcL + 1]);
                        ((uint4*)preh)[(size_t)m * 32 + (wn * 8 + hh * 4 + tig)] = u;
                    }
                }
        }
    }
}

// ---------------- persistent fused LSTM chain: 32-row tiles, tickets --------------
#define CHAIN_SMEM (160 * 1024)
__global__ __launch_bounds__(512, 1) void k_chain(const float* __restrict__ Wr1,
                                                  const float* __restrict__ Wroot1,
                                                  const float* __restrict__ Wr2,
                                                  const float* __restrict__ Wroot2,
                                                  float* __restrict__ outC2) {
    extern __shared__ unsigned smem[];
    unsigned* sW = smem;                      // 16384 u32
    unsigned* sA = smem + 8 * 32 * 32 * 2;    // 2048 u32 (32-row tile)
    __shared__ int sTicket;
    int tid = threadIdx.x;
    int warp = tid >> 5, lane = tid & 31;
    int wm = warp >> 3, wn = warp & 7;        // 2 x 8 warps over 32x256 tile
    int gid = lane >> 2, tig = lane & 3;
    unsigned gen = g_bar_gen;

    // init h0, c0, per-step tickets
    for (int i = blockIdx.x * 512 + tid; i < NN * 32; i += gridDim.x * 512)
        g_hh[0][i] = 0u;
    for (int i = blockIdx.x * 512 + tid; i < NN * HH; i += gridDim.x * 512)
        g_c[i] = 0.f;
    if (blockIdx.x == 0 && tid < 2 * TT) g_ctr[tid] = 0;
    gridbar(gen);

    int par = 0;
    for (int L = 0; L < 2; L++) {
        const float* __restrict__ Wr = L ? Wr2 : Wr1;
        const float* __restrict__ Wroot = L ? Wroot2 : Wroot1;
        for (int i = tid; i < 64 * 256; i += 512) {
            int k2 = i >> 8, n = i & 255;
            int k = k2 * 2;
            float v0, v1;
            if (k < 64) {
                v0 = Wr[(size_t)(64 + k) * 256 + n];
                v1 = Wr[(size_t)(65 + k) * 256 + n];
            } else {
                v0 = Wroot[(size_t)k * 256 + n];
                v1 = Wroot[(size_t)(k + 1) * 256 + n];
            }
            int kc = k2 >> 3, breg = (k2 >> 2) & 1;
            int bl = (n & 7) * 4 + (k2 & 3);
            sW[((kc * 32 + (n >> 3)) * 32 + bl) * 2 + breg] = h2u(v0, v1);
        }
        __syncthreads();
        const unsigned* __restrict__ preL = g_preh[L];

        for (int t = 0; t < TT; t++) {
            const unsigned* __restrict__ hin = g_hh[par];
            unsigned* __restrict__ hout = g_hh[par ^ 1];
            const uint4* __restrict__ pre4 =
                (const uint4*)(preL + (size_t)t * NN * 128);
            int store = (L == 1 && t >= TT - 4) ? (t - (TT - 4)) : -1;
            int step_id = L * TT + t;

            for (;;) {
                __syncthreads();   // previous tile fully consumed before re-staging
                if (tid == 0) sTicket = atomicAdd(&g_ctr[step_id], 1);
                __syncthreads();
                int tile = sTicket;
                if (tile >= CH_TILES) break;
                int m0 = tile * 32;

                // prefetch pre-activations (addresses known now; hide DRAM latency)
                int mP0 = m0 + wm * 16 + gid;
                int pidx = wn * 4 + tig;
                uint4 p4A = __ldg(&pre4[(size_t)mP0 * 32 + pidx]);
                uint4 p4B = __ldg(&pre4[(size_t)(mP0 + 8) * 32 + pidx]);

                // gather: 16 warps x 2 rows; lane = feature pair (MLP-4 + tail)
#pragma unroll
                for (int rq = 0; rq < 2; rq++) {
                    int r = warp * 2 + rq;
                    int m = m0 + r;
                    int e0 = g_rowptr[m], e1 = g_rowptr[m + 1];
                    float ax = 0.f, ay = 0.f;
                    int e = e0;
                    for (; e + 4 <= e1; e += 4) {
                        int s0 = __ldg(&g_csr_src[e]);
                        int s1 = __ldg(&g_csr_src[e + 1]);
                        int s2 = __ldg(&g_csr_src[e + 2]);
                        int s3 = __ldg(&g_csr_src[e + 3]);
                        float w0 = __ldg(&g_csr_w[e]);
                        float w1 = __ldg(&g_csr_w[e + 1]);
                        float w2 = __ldg(&g_csr_w[e + 2]);
                        float w3 = __ldg(&g_csr_w[e + 3]);
                        float2 v0 = u2f2(__ldg(&hin[(size_t)s0 * 32 + lane]));
                        float2 v1 = u2f2(__ldg(&hin[(size_t)s1 * 32 + lane]));
                        float2 v2 = u2f2(__ldg(&hin[(size_t)s2 * 32 + lane]));
                        float2 v3 = u2f2(__ldg(&hin[(size_t)s3 * 32 + lane]));
                        ax += w0 * v0.x + w1 * v1.x + w2 * v2.x + w3 * v3.x;
                        ay += w0 * v0.y + w1 * v1.y + w2 * v2.y + w3 * v3.y;
                    }
                    for (; e < e1; e++) {
                        int s = __ldg(&g_csr_src[e]);
                        float w = __ldg(&g_csr_w[e]);
                        float2 v = u2f2(__ldg(&hin[(size_t)s * 32 + lane]));
                        ax += w * v.x;
                        ay += w * v.y;
                    }
                    float inv = 1.f / (float)max(e1 - e0, 1);
                    unsigned aggu = h2u(ax * inv, ay * inv);
                    unsigned hu = hin[(size_t)m * 32 + lane];
                    int mf = r >> 4;
                    int al = (r & 7) * 4 + (lane & 3);
                    int regc = ((lane >> 2) & 1) * 2 + ((r >> 3) & 1);
                    int kcA = lane >> 3;
                    sA[((mf * 8 + kcA) * 32 + al) * 4 + regc] = aggu;
                    sA[((mf * 8 + 4 + kcA) * 32 + al) * 4 + regc] = hu;
                }
                __syncthreads();
                float acc[4][4];
#pragma unroll
                for (int g = 0; g < 4; g++)
#pragma unroll
                    for (int q = 0; q < 4; q++) acc[g][q] = 0.f;
#pragma unroll
                for (int kc = 0; kc < 8; kc++) {
                    uint4 a = ((const uint4*)sA)[(wm * 8 + kc) * 32 + lane];
#pragma unroll
                    for (int g = 0; g < 4; g++) {
                        int n8 = g * 8 + wn;
                        uint2 b = ((const uint2*)sW)[(kc * 32 + n8) * 32 + lane];
                        mma16(acc[g], a, b);
                    }
                }
#pragma unroll
                for (int rr = 0; rr < 2; rr++) {
                    int m = m0 + wm * 16 + gid + rr * 8;
                    int hc = wn * 8 + tig * 2;
                    uint4 p4 = rr ? p4B : p4A;
                    float2 pi = u2f2(p4.x);
                    float2 pf = u2f2(p4.y);
                    float2 pg = u2f2(p4.z);
                    float2 po = u2f2(p4.w);
                    size_t hb = (size_t)m * 64 + hc;
                    float2 cold = *(const float2*)&g_c[hb];
                    float gi0 = acc[0][rr * 2 + 0] + pi.x;
                    float gi1 = acc[0][rr * 2 + 1] + pi.y;
                    float gf0 = acc[1][rr * 2 + 0] + pf.x;
                    float gf1 = acc[1][rr * 2 + 1] + pf.y;
                    float gg0 = acc[2][rr * 2 + 0] + pg.x;
                    float gg1 = acc[2][rr * 2 + 1] + pg.y;
                    float go0 = acc[3][rr * 2 + 0] + po.x;
                    float go1 = acc[3][rr * 2 + 1] + po.y;
                    float si0 = __fdividef(1.f, 1.f + __expf(-gi0));
                    float si1 = __fdividef(1.f, 1.f + __expf(-gi1));
                    float sf0 = __fdividef(1.f, 1.f + __expf(-gf0));
                    float sf1 = __fdividef(1.f, 1.f + __expf(-gf1));
                    float so0 = __fdividef(1.f, 1.f + __expf(-go0));
                    float so1 = __fdividef(1.f, 1.f + __expf(-go1));
                    float2 cn, hn;
                    cn.x = sf0 * cold.x + si0 * tanhf(gg0);
                    cn.y = sf1 * cold.y + si1 * tanhf(gg1);
                    hn.x = so0 * tanhf(cn.x);
                    hn.y = so1 * tanhf(cn.y);
                    *(float2*)&g_c[hb] = cn;
                    hout[(size_t)m * 32 + (hc >> 1)] = h2u(hn.x, hn.y);
                    if (store >= 0)
                        *(float2*)&g_h2last[(size_t)store * NN * 64 + hb] = hn;
                }
            }
            gridbar(gen);
            par ^= 1;
        }
        __syncthreads();
    }

    for (int i = blockIdx.x * 512 + tid; i < NN * HH; i += gridDim.x * 512)
        outC2[i] = g_c[i];
}

// ---------------- final projection: out = [relu(emb), h2][-4:] @ W_out + b_out ----
__global__ __launch_bounds__(256) void k_out(const float* __restrict__ emb,
                                             const float* __restrict__ Wout,
                                             const float* __restrict__ bout,
                                             float* __restrict__ out) {
    __shared__ float sX[32][129];
    __shared__ float sW[128][9];
    int tt = blockIdx.y;
    int n0 = blockIdx.x * 32;
    int tid = threadIdx.x;
    for (int i = tid; i < 32 * 64; i += 256) {
        int r = i >> 6, k = i & 63;
        int m = n0 + r;
        sX[r][k] = (m < NN)
            ? fmaxf(emb[((size_t)(TT - 4 + tt) * NN + m) * 64 + k], 0.f) : 0.f;
        sX[r][64 + k] = (m < NN) ? g_h2last[((size_t)tt * NN + m) * 64 + k] : 0.f;
    }
    for (int i = tid; i < 128 * 8; i += 256) sW[i >> 3][i & 7] = Wout[i];
    __syncthreads();
    int node = tid >> 3, o = tid & 7;
    float acc = bout[o];
    for (int k = 0; k < 128; k++) acc += sX[node][k] * sW[k][o];
    int m = n0 + node;
    if (m < NN) out[((size_t)tt * NN + m) * 8 + o] = acc;
}

// ---------------- launch ----------------------------------------------------------
extern "C" void kernel_launch(void* const* d_in, const int* in_sizes, int n_in,
                              void* d_out, int out_size) {
    const float* x      = (const float*)d_in[0];
    const int*   ei     = (const int*)d_in[1];
    const float* ew     = (const float*)d_in[2];
    const float* sWr    = (const float*)d_in[3];
    const float* sWroot = (const float*)d_in[4];
    const float* sb     = (const float*)d_in[5];
    const float* Wr1    = (const float*)d_in[6];
    const float* Wroot1 = (const float*)d_in[7];
    const float* b1     = (const float*)d_in[8];
    const float* Wr2    = (const float*)d_in[9];
    const float* Wroot2 = (const float*)d_in[10];
    const float* b2     = (const float*)d_in[11];
    const float* Wout   = (const float*)d_in[12];
    const float* bout   = (const float*)d_in[13];
    float* out = (float*)d_out;
    const int* src = ei;
    const int* dst = ei + EE;

    int nsm = 0;
    cudaDeviceGetAttribute(&nsm, cudaDevAttrMultiProcessorCount, 0);
    cudaFuncSetAttribute(k_chain, cudaFuncAttributeMaxDynamicSharedMemorySize,
                         CHAIN_SMEM);
    cudaFuncSetAttribute(k_pre, cudaFuncAttributeMaxDynamicSharedMemorySize,
                         PRE_SMEM);

    // CSR build
    k_zero_cursor<<<(NN + 255) / 256, 256>>>();
    k_deg<<<(EE + 255) / 256, 256>>>(dst);
    k_scan<<<1, 1024>>>();
    k_fill<<<(EE + 255) / 256, 256>>>(src, dst, ew);

    // SAGE embedding (exact fp32 -> emb; fp16 xr)
    dim3 aggGridT(2500, TT);
    k_aggx<<<aggGridT, 256>>>(x);
    k_sage<<<TT * NN / 64, 256>>>(x, sWr, sWroot, sb, out + EMB_OFF);

    // x-dependent gate halves (fp16 agg + fp16 mma + gate-interleaved fp16 pre)
    k_aggh<<<aggGridT, 256>>>();
    k_pre<<<nsm, 512, PRE_SMEM>>>(Wr1, Wroot1, b1, Wr2, Wroot2, b2);

    // Fused persistent chain (tickets + prefetched uint4 pre reads)
    k_chain<<<nsm, 512, CHAIN_SMEM>>>(Wr1, Wroot1, Wr2, Wroot2, out + C2_OFF);

    k_out<<<dim3(NN / 32, 4), 256>>>(out + EMB_OFF, Wout, bout, out + OUT_OFF);
}